// round 9
// baseline (speedup 1.0000x reference)
#include <cuda_runtime.h>

// 0: x [2,192,88,133] f32, 1: W_lin [133,24], 2: b_lin [24], 3: W_qkv [24,72],
// 4: b_qkv [72], 5: rpb [4,49,49], 6: W_proj [24,24], 7: b_proj [24]
// output: [2,192,88,24] f32

#define BB   2
#define HT   192
#define WD   88
#define FIN  133
#define CC   24
#define NH   4
#define DH   6
#define WIN  25
#define NPIX (BB*HT*WD)   // 33792
#define RPBW 49
#define TR   3            // query rows per attn block
#define NTA  176          // attn threads: 44 cols x 4 heads
#define KW   56           // staged key cols per block (j-half window union)
#define KVT  (CC*KW)      // 1344 floats per K (or V) row tile
#define BROWS 29
#define BH   (BROWS*RPBW) // 1421
#define LOG2E 1.4426950408889634f

typedef unsigned long long ull;

// Scratch (device globals: allocation-free)
__device__ float g_q [NPIX*CC], g_k [NPIX*CC], g_v [NPIX*CC];  // [bi][ch][col]
__device__ float g_q2[NPIX*CC], g_k2[NPIX*CC], g_v2[NPIX*CC];
__device__ float g_wc[CC*72], g_bc[72];

// ---- packed f32x2 helpers --------------------------------------------------
__device__ __forceinline__ ull pk2(float lo, float hi) {
    ull r; asm("mov.b64 %0, {%1,%2};" : "=l"(r) : "f"(lo), "f"(hi)); return r;
}
__device__ __forceinline__ ull bc2(float v) { return pk2(v, v); }
__device__ __forceinline__ void upk2(float& lo, float& hi, ull v) {
    asm("mov.b64 {%0,%1}, %2;" : "=f"(lo), "=f"(hi) : "l"(v));
}
__device__ __forceinline__ ull fma2(ull a, ull b, ull c) {
    ull d; asm("fma.rn.f32x2 %0, %1, %2, %3;" : "=l"(d) : "l"(a), "l"(b), "l"(c)); return d;
}
__device__ __forceinline__ ull add2(ull a, ull b) {
    ull d; asm("add.rn.f32x2 %0, %1, %2;" : "=l"(d) : "l"(a), "l"(b)); return d;
}
__device__ __forceinline__ ull mul2(ull a, ull b) {
    ull d; asm("mul.rn.f32x2 %0, %1, %2;" : "=l"(d) : "l"(a), "l"(b)); return d;
}
__device__ __forceinline__ float ex2f(float x) {
    float y; asm("ex2.approx.f32 %0, %1;" : "=f"(y) : "f"(x)); return y;
}
__device__ __forceinline__ ull lds64(const float* p) {
    return *reinterpret_cast<const ull*>(p);   // even float offset from 16B base
}

// ---------------------------------------------------------------------------
// Setup: Wcomb = W_proj @ W_qkv, bcomb = b_proj @ W_qkv + b_qkv
// (q columns scaled by dh^-0.5 * log2(e) for raw ex2 in attention)
// ---------------------------------------------------------------------------
__global__ void k_comb(const float* __restrict__ Wp, const float* __restrict__ bp,
                       const float* __restrict__ Wq, const float* __restrict__ bq) {
    int t = blockIdx.x * blockDim.x + threadIdx.x;
    const float QS = 0.40824829046386302f * LOG2E;
    if (t < CC*72) {
        int u = t / 72, cf = t % 72;
        float a = 0.f;
        #pragma unroll
        for (int w = 0; w < CC; ++w) a = fmaf(Wp[u*CC + w], Wq[w*72 + cf], a);
        if (cf < CC) a *= QS;
        g_wc[t] = a;
    }
    if (t < 72) {
        float a = bq[t];
        #pragma unroll
        for (int w = 0; w < CC; ++w) a = fmaf(bp[w], Wq[w*72 + t], a);
        if (t < CC) a *= QS;
        g_bc[t] = a;
    }
}

// ---------------------------------------------------------------------------
// Fused linear+ReLU+qkv: block = 44-pixel half row. Writes d-major q/k/v.
// ---------------------------------------------------------------------------
__global__ void __launch_bounds__(352) k_linqkv(const float* __restrict__ x,
                                                const float* __restrict__ Wl,
                                                const float* __restrict__ bl,
                                                const float* __restrict__ Wq,
                                                const float* __restrict__ bq) {
    __shared__ float sm[11872];
    float* xs = sm;               // 44*133 = 5852
    float* wl = sm + 5852;        // 133*24 = 3192
    float* hs = sm + 9044;        // 44*25  = 1100
    float* wq = sm + 10144;       // 24*72  = 1728

    int blk = blockIdx.x;
    int bi = blk >> 1, jb = (blk & 1) * 44;
    int tid = threadIdx.x;

    const float* xb = x + ((size_t)bi * WD + jb) * FIN;
    for (int idx = tid; idx < 44*FIN; idx += 352) xs[idx] = xb[idx];
    for (int idx = tid; idx < FIN*CC; idx += 352) wl[idx] = Wl[idx];
    for (int idx = tid; idx < CC*72; idx += 352) wq[idx] = Wq[idx];
    __syncthreads();

    int jl = tid % 44, cg = tid / 44;      // cg in [0,8): 3 channels each
    int c0 = cg * 3;
    float acc[3];
    #pragma unroll
    for (int i = 0; i < 3; ++i) acc[i] = bl[c0 + i];
    #pragma unroll 7
    for (int f = 0; f < FIN; ++f) {
        float xf = xs[jl*FIN + f];
        #pragma unroll
        for (int i = 0; i < 3; ++i) acc[i] = fmaf(xf, wl[f*CC + c0 + i], acc[i]);
    }
    #pragma unroll
    for (int i = 0; i < 3; ++i) hs[jl*25 + c0 + i] = fmaxf(acc[i], 0.f);
    __syncthreads();

    const float QS = 0.40824829046386302f * LOG2E;
    for (int o = tid; o < 44*72; o += 352) {
        int cf = o / 44, j2 = o - cf*44;
        float a = bq[cf];
        #pragma unroll
        for (int u = 0; u < CC; ++u) a = fmaf(hs[j2*25 + u], wq[u*72 + cf], a);
        if (cf < CC) a *= QS;
        int which = cf / CC, ch = cf % CC;
        float* dst = (which == 0) ? g_q : (which == 1) ? g_k : g_v;
        dst[((size_t)bi * CC + ch) * WD + jb + j2] = a;
    }
}

// ---------------------------------------------------------------------------
// Attention: block = (b, i-triple, j-half). 176 thr = 44 j x 4 h, 2 blocks/SM.
// Double-buffered K/V staging -> ONE barrier per key row; cross-block overlap
// hides the barrier. f32x2 over column pairs, log2-domain scores, raw ex2.
// MODE 0: epilogue -> layer-2 qkv via Wcomb. MODE 1: final projection.
// ---------------------------------------------------------------------------
template<int MODE>
__global__ void __launch_bounds__(NTA, 2) k_attn(
    const float* __restrict__ Q, const float* __restrict__ K,
    const float* __restrict__ V, const float* __restrict__ rpb,
    const float* __restrict__ W, const float* __restrict__ bvec,
    float* __restrict__ outp)
{
    __shared__ __align__(16) float smem[11060];
    float* bias_s = smem;                  // 5684 (scaled by log2e)
    // K/V double buffers: buf p at 5684 + p*2*KVT (k), +KVT (v)

    int blk = blockIdx.x;                  // 256 blocks
    int jh = blk & 1;
    int rest = blk >> 1;
    int b = rest >> 6, it = rest & 63;
    int i0 = it * TR;
    int jb = jh * 44, colbase = jh * 32;
    int tid = threadIdx.x;
    int jl = tid % 44, h = tid / 44;
    int j = jb + jl, h6 = h * DH;

    int sii[TR];
    #pragma unroll
    for (int t = 0; t < TR; ++t) sii[t] = min(max(i0 + t - 12, 0), HT - WIN);
    int r_lo = sii[0];
    int nrows = sii[2] + WIN - r_lo;       // 25..27
    int row_base = r_lo - i0 + 22;

    int sjj = min(max(j - 12, 0), WD - WIN);
    int e0 = sjj & 1;
    int c0 = sjj - e0;                     // even absolute window start
    int scol = c0 - colbase;               // [0,30] even, +25 fits in KW=56
    int cb = c0 + 24 - j;                  // bias column base

    for (int idx = tid; idx < NH*BH; idx += NTA) {
        int hh = idx / BH, rem = idx - hh*BH;
        int rr = rem / RPBW, c = rem - rr*RPBW;
        int src = min(max(row_base + rr, 0), RPBW - 1);
        bias_s[idx] = rpb[hh*RPBW*RPBW + src*RPBW + c] * LOG2E;
    }

    // q vectors (broadcast-packed) + negated center scores (log2 units)
    float nsc[TR];
    ull qb2[TR][DH];
    #pragma unroll
    for (int t = 0; t < TR; ++t) {
        const float* qb = Q + ((size_t)(b*HT + i0 + t) * CC + h6) * WD + j;
        const float* kc = K + ((size_t)(b*HT + i0 + t) * CC + h6) * WD + j;
        float s = 0.f;
        #pragma unroll
        for (int d = 0; d < DH; ++d) {
            float qd = qb[d*WD];
            s = fmaf(qd, kc[d*WD], s);
            qb2[t][d] = bc2(qd);
        }
        nsc[t] = -s;
    }

    // edge masks (thread-constant)
    ull mfirst = pk2(e0 ? 0.f : 1.f, 1.f);
    ull mlast  = pk2(1.f, e0 ? 1.f : 0.f);

    ull accp[TR][DH], lp[TR];
    #pragma unroll
    for (int t = 0; t < TR; ++t) {
        lp[t] = 0ULL;
        #pragma unroll
        for (int d = 0; d < DH; ++d) accp[t][d] = 0ULL;
    }

    // row-invariant staging offsets: idx -> ch*WD + colbase + c (idx = ch*KW+c)
    int offu[8], sidx[8];
    #pragma unroll
    for (int u = 0; u < 8; ++u) {
        int idx = tid + u*NTA;
        sidx[u] = idx;
        offu[u] = (idx < KVT) ? (idx / KW) * WD + colbase + (idx % KW) : -1;
    }

    // prefetch first row into registers
    float kr[8], vr[8];
    {
        size_t rb = (size_t)(b*HT + r_lo) * CC * WD;
        #pragma unroll
        for (int u = 0; u < 8; ++u)
            if (offu[u] >= 0) { kr[u] = K[rb + offu[u]]; vr[u] = V[rb + offu[u]]; }
    }

    for (int rr = 0; rr < nrows; ++rr) {
        int r = r_lo + rr;
        float* kbuf = smem + 5684 + (rr & 1) * (2*KVT);
        float* vbuf = kbuf + KVT;

        #pragma unroll
        for (int u = 0; u < 8; ++u)
            if (sidx[u] < KVT) { kbuf[sidx[u]] = kr[u]; vbuf[sidx[u]] = vr[u]; }
        __syncthreads();                   // single barrier per row

        if (rr + 1 < nrows) {              // prefetch next row during compute
            size_t rb = (size_t)(b*HT + r + 1) * CC * WD;
            #pragma unroll
            for (int u = 0; u < 8; ++u)
                if (offu[u] >= 0) { kr[u] = K[rb + offu[u]]; vr[u] = V[rb + offu[u]]; }
        }

        // per-row shifts (row-validity kill, log2 units)
        ull shp[TR];
        shp[0] = bc2(nsc[0] + ((r <= sii[0] + 24) ? 0.f : -87.f));
        shp[1] = bc2(nsc[1] + ((r >= sii[1] && r <= sii[1] + 24) ? 0.f : -87.f));
        shp[2] = bc2(nsc[2] + ((r >= sii[2]) ? 0.f : -87.f));

        const float* kb = kbuf + h6*KW + scol;
        const float* vb = vbuf + h6*KW + scol;
        const float* br0 = bias_s + h*BH + (rr + 2)*RPBW + cb;  // query 0
        const float* br1 = br0 - RPBW;
        const float* br2 = br1 - RPBW;

        #pragma unroll
        for (int p = 0; p < 13; ++p) {
            ull kpair[DH], vpair[DH];
            #pragma unroll
            for (int d = 0; d < DH; ++d) {
                kpair[d] = lds64(kb + d*KW + 2*p);
                vpair[d] = lds64(vb + d*KW + 2*p);
            }
            #pragma unroll
            for (int t = 0; t < TR; ++t) {
                const float* br = (t == 0) ? br0 : (t == 1) ? br1 : br2;
                ull s = add2(pk2(br[2*p], br[2*p + 1]), shp[t]);
                #pragma unroll
                for (int d = 0; d < DH; ++d) s = fma2(qb2[t][d], kpair[d], s);
                float s0, s1; upk2(s0, s1, s);
                ull pp = pk2(ex2f(s0), ex2f(s1));
                if (p == 0)  pp = mul2(pp, mfirst);
                if (p == 12) pp = mul2(pp, mlast);
                lp[t] = add2(lp[t], pp);
                #pragma unroll
                for (int d = 0; d < DH; ++d) accp[t][d] = fma2(pp, vpair[d], accp[t][d]);
            }
        }
    }

    // ---- epilogue (reuses bias_s region; K/V buffers untouched) ------------
    __syncthreads();
    float* attn_s = smem;                  // [3][44][25] = 3300
    const int NOUT = (MODE == 0) ? 72 : 24;
    float* ws = smem + 3328;               // <=1728
    float* bs = smem + 3328 + 1728;        // <=72
    #pragma unroll
    for (int t = 0; t < TR; ++t) {
        float l0, l1; upk2(l0, l1, lp[t]);
        float inv = __fdividef(1.f, l0 + l1);
        #pragma unroll
        for (int d = 0; d < DH; ++d) {
            float a0, a1; upk2(a0, a1, accp[t][d]);
            attn_s[(t*44 + jl)*25 + h6 + d] = (a0 + a1) * inv;
        }
    }
    for (int idx = tid; idx < CC*NOUT; idx += NTA) ws[idx] = W[idx];
    for (int idx = tid; idx < NOUT; idx += NTA) bs[idx] = bvec[idx];
    __syncthreads();

    if (MODE == 0) {
        #pragma unroll
        for (int pass = 0; pass < 3; ++pass) {
            int cf0 = h * 18 + pass * 6;
            float acc[TR][6];
            #pragma unroll
            for (int t = 0; t < TR; ++t)
                #pragma unroll
                for (int ci = 0; ci < 6; ++ci) acc[t][ci] = bs[cf0 + ci];
            #pragma unroll
            for (int u = 0; u < CC; ++u) {
                float wv[6], av[TR];
                #pragma unroll
                for (int ci = 0; ci < 6; ++ci) wv[ci] = ws[u*72 + cf0 + ci];
                #pragma unroll
                for (int t = 0; t < TR; ++t) av[t] = attn_s[(t*44 + jl)*25 + u];
                #pragma unroll
                for (int t = 0; t < TR; ++t)
                    #pragma unroll
                    for (int ci = 0; ci < 6; ++ci)
                        acc[t][ci] = fmaf(av[t], wv[ci], acc[t][ci]);
            }
            int which = (cf0 >= 48) ? 2 : (cf0 >= 24 ? 1 : 0);
            int chb = cf0 - which * CC;
            float* dst = (which == 0) ? g_q2 : (which == 1) ? g_k2 : g_v2;
            #pragma unroll
            for (int t = 0; t < TR; ++t)
                #pragma unroll
                for (int ci = 0; ci < 6; ++ci)
                    dst[((size_t)(b*HT + i0 + t) * CC + chb + ci) * WD + j] = acc[t][ci];
        }
    } else {
        int cf0 = h * 6;
        float acc[TR][6];
        #pragma unroll
        for (int t = 0; t < TR; ++t)
            #pragma unroll
            for (int ci = 0; ci < 6; ++ci) acc[t][ci] = bs[cf0 + ci];
        #pragma unroll
        for (int u = 0; u < CC; ++u) {
            float wv[6], av[TR];
            #pragma unroll
            for (int ci = 0; ci < 6; ++ci) wv[ci] = ws[u*24 + cf0 + ci];
            #pragma unroll
            for (int t = 0; t < TR; ++t) av[t] = attn_s[(t*44 + jl)*25 + u];
            #pragma unroll
            for (int t = 0; t < TR; ++t)
                #pragma unroll
                for (int ci = 0; ci < 6; ++ci)
                    acc[t][ci] = fmaf(av[t], wv[ci], acc[t][ci]);
        }
        __syncthreads();
        float* res_s = smem;               // [3][44][24] = 3168
        #pragma unroll
        for (int t = 0; t < TR; ++t)
            #pragma unroll
            for (int ci = 0; ci < 6; ++ci)
                res_s[(t*44 + jl)*24 + cf0 + ci] = acc[t][ci];
        __syncthreads();
        // coalesced: per t, 44*24 contiguous floats at (row i0+t, col jb)
        for (int o = tid; o < TR*44*CC; o += NTA) {
            int t = o / (44*CC), rem = o - t*(44*CC);
            outp[((size_t)(b*HT + i0 + t) * WD + jb) * CC + rem] = res_s[o];
        }
    }
}

// ---------------------------------------------------------------------------
extern "C" void kernel_launch(void* const* d_in, const int* in_sizes, int n_in,
                              void* d_out, int out_size) {
    (void)in_sizes; (void)n_in; (void)out_size;
    const float* x      = (const float*)d_in[0];
    const float* W_lin  = (const float*)d_in[1];
    const float* b_lin  = (const float*)d_in[2];
    const float* W_qkv  = (const float*)d_in[3];
    const float* b_qkv  = (const float*)d_in[4];
    const float* rpb    = (const float*)d_in[5];
    const float* W_proj = (const float*)d_in[6];
    const float* b_proj = (const float*)d_in[7];
    float* out = (float*)d_out;

    float *q, *k, *v, *q2, *k2, *v2, *wc, *bc;
    cudaGetSymbolAddress((void**)&q,  g_q);
    cudaGetSymbolAddress((void**)&k,  g_k);
    cudaGetSymbolAddress((void**)&v,  g_v);
    cudaGetSymbolAddress((void**)&q2, g_q2);
    cudaGetSymbolAddress((void**)&k2, g_k2);
    cudaGetSymbolAddress((void**)&v2, g_v2);
    cudaGetSymbolAddress((void**)&wc, g_wc);
    cudaGetSymbolAddress((void**)&bc, g_bc);

    k_comb<<<7, 256>>>(W_proj, b_proj, W_qkv, b_qkv);
    k_linqkv<<<BB*HT*2, 352>>>(x, W_lin, b_lin, W_qkv, b_qkv);
    k_attn<0><<<256, NTA>>>(q,  k,  v,  rpb, wc,     bc,     nullptr);
    k_attn<1><<<256, NTA>>>(q2, k2, v2, rpb, W_proj, b_proj, out);
}

// round 10
// speedup vs baseline: 1.1596x; 1.1596x over previous
#include <cuda_runtime.h>

// 0: x [2,192,88,133] f32, 1: W_lin [133,24], 2: b_lin [24], 3: W_qkv [24,72],
// 4: b_qkv [72], 5: rpb [4,49,49], 6: W_proj [24,24], 7: b_proj [24]
// output: [2,192,88,24] f32

#define BB   2
#define HT   192
#define WD   88
#define FIN  133
#define CC   24
#define NH   4
#define DH   6
#define WIN  25
#define NPIX (BB*HT*WD)   // 33792
#define RPBW 49
#define TR   3            // query rows per attn block
#define NT   352          // attn threads: 88 cols x 4 heads
#define BROWS 29
#define BH   (BROWS*RPBW) // 1421
#define LOG2E 1.4426950408889634f

typedef unsigned long long ull;

// Scratch (device globals: allocation-free)
__device__ float g_q [NPIX*CC], g_k [NPIX*CC], g_v [NPIX*CC];  // [bi][ch][col]
__device__ float g_q2[NPIX*CC], g_k2[NPIX*CC], g_v2[NPIX*CC];
__device__ float g_wc[CC*72], g_bc[72];

// ---- packed f32x2 helpers --------------------------------------------------
__device__ __forceinline__ ull pk2(float lo, float hi) {
    ull r; asm("mov.b64 %0, {%1,%2};" : "=l"(r) : "f"(lo), "f"(hi)); return r;
}
__device__ __forceinline__ ull bc2(float v) { return pk2(v, v); }
__device__ __forceinline__ void upk2(float& lo, float& hi, ull v) {
    asm("mov.b64 {%0,%1}, %2;" : "=f"(lo), "=f"(hi) : "l"(v));
}
__device__ __forceinline__ ull fma2(ull a, ull b, ull c) {
    ull d; asm("fma.rn.f32x2 %0, %1, %2, %3;" : "=l"(d) : "l"(a), "l"(b), "l"(c)); return d;
}
__device__ __forceinline__ ull add2(ull a, ull b) {
    ull d; asm("add.rn.f32x2 %0, %1, %2;" : "=l"(d) : "l"(a), "l"(b)); return d;
}
__device__ __forceinline__ ull mul2(ull a, ull b) {
    ull d; asm("mul.rn.f32x2 %0, %1, %2;" : "=l"(d) : "l"(a), "l"(b)); return d;
}
__device__ __forceinline__ float ex2f(float x) {
    float y; asm("ex2.approx.f32 %0, %1;" : "=f"(y) : "f"(x)); return y;
}
__device__ __forceinline__ ull lds64(const float* p) {
    return *reinterpret_cast<const ull*>(p);   // even float offset from 16B base
}

// ---------------------------------------------------------------------------
// Setup: Wcomb = W_proj @ W_qkv, bcomb = b_proj @ W_qkv + b_qkv
// (q columns scaled by dh^-0.5 * log2(e) for raw ex2 in attention)
// ---------------------------------------------------------------------------
__global__ void k_comb(const float* __restrict__ Wp, const float* __restrict__ bp,
                       const float* __restrict__ Wq, const float* __restrict__ bq) {
    int t = blockIdx.x * blockDim.x + threadIdx.x;
    const float QS = 0.40824829046386302f * LOG2E;
    if (t < CC*72) {
        int u = t / 72, cf = t % 72;
        float a = 0.f;
        #pragma unroll
        for (int w = 0; w < CC; ++w) a = fmaf(Wp[u*CC + w], Wq[w*72 + cf], a);
        if (cf < CC) a *= QS;
        g_wc[t] = a;
    }
    if (t < 72) {
        float a = bq[t];
        #pragma unroll
        for (int w = 0; w < CC; ++w) a = fmaf(bp[w], Wq[w*72 + t], a);
        if (t < CC) a *= QS;
        g_bc[t] = a;
    }
}

// ---------------------------------------------------------------------------
// Fused linear+ReLU+qkv: block = 44-pixel half row. Writes d-major q/k/v.
// ---------------------------------------------------------------------------
__global__ void __launch_bounds__(352) k_linqkv(const float* __restrict__ x,
                                                const float* __restrict__ Wl,
                                                const float* __restrict__ bl,
                                                const float* __restrict__ Wq,
                                                const float* __restrict__ bq) {
    __shared__ float sm[11872];
    float* xs = sm;               // 44*133 = 5852
    float* wl = sm + 5852;        // 133*24 = 3192
    float* hs = sm + 9044;        // 44*25  = 1100
    float* wq = sm + 10144;       // 24*72  = 1728

    int blk = blockIdx.x;
    int bi = blk >> 1, jb = (blk & 1) * 44;
    int tid = threadIdx.x;

    const float* xb = x + ((size_t)bi * WD + jb) * FIN;
    for (int idx = tid; idx < 44*FIN; idx += 352) xs[idx] = xb[idx];
    for (int idx = tid; idx < FIN*CC; idx += 352) wl[idx] = Wl[idx];
    for (int idx = tid; idx < CC*72; idx += 352) wq[idx] = Wq[idx];
    __syncthreads();

    int jl = tid % 44, cg = tid / 44;      // cg in [0,8): 3 channels each
    int c0 = cg * 3;
    float acc[3];
    #pragma unroll
    for (int i = 0; i < 3; ++i) acc[i] = bl[c0 + i];
    #pragma unroll 7
    for (int f = 0; f < FIN; ++f) {
        float xf = xs[jl*FIN + f];
        #pragma unroll
        for (int i = 0; i < 3; ++i) acc[i] = fmaf(xf, wl[f*CC + c0 + i], acc[i]);
    }
    #pragma unroll
    for (int i = 0; i < 3; ++i) hs[jl*25 + c0 + i] = fmaxf(acc[i], 0.f);
    __syncthreads();

    const float QS = 0.40824829046386302f * LOG2E;
    for (int o = tid; o < 44*72; o += 352) {
        int cf = o / 44, j2 = o - cf*44;
        float a = bq[cf];
        #pragma unroll
        for (int u = 0; u < CC; ++u) a = fmaf(hs[j2*25 + u], wq[u*72 + cf], a);
        if (cf < CC) a *= QS;
        int which = cf / CC, ch = cf % CC;
        float* dst = (which == 0) ? g_q : (which == 1) ? g_k : g_v;
        dst[((size_t)bi * CC + ch) * WD + jb + j2] = a;
    }
}

// ---------------------------------------------------------------------------
// Attention (TR=3, 352 thr, grid 128): K staged in smem with DOUBLE BUFFER
// (one __syncthreads per key row); V read directly via LDG.64 (pair-aligned,
// L1-warmed one row ahead). f32x2 over column pairs; log2-domain scores; ex2.
// MODE 0: epilogue -> layer-2 qkv via Wcomb. MODE 1: final projection.
// ---------------------------------------------------------------------------
template<int MODE>
__global__ void __launch_bounds__(NT, 1) k_attn(
    const float* __restrict__ Q, const float* __restrict__ K,
    const float* __restrict__ V, const float* __restrict__ rpb,
    const float* __restrict__ W, const float* __restrict__ bvec,
    float* __restrict__ outp)
{
    __shared__ __align__(16) float smem[9908];
    float* bias_s = smem;           // 4*29*49 = 5684 (scaled by log2e)
    // K double buffers at 5684 + p*2112

    int blk = blockIdx.x;           // 128 blocks
    int b = blk >> 6, it = blk & 63;
    int i0 = it * TR;
    int tid = threadIdx.x;
    int j = tid % WD, h = tid / WD, h6 = h * DH;

    int sii[TR];
    #pragma unroll
    for (int t = 0; t < TR; ++t) sii[t] = min(max(i0 + t - 12, 0), HT - WIN);
    int r_lo = sii[0];
    int nrows = sii[2] + WIN - r_lo;           // 25..27
    int row_base = r_lo - i0 + 22;

    int sjj = min(max(j - 12, 0), WD - WIN);
    int e0 = sjj & 1;
    int c0 = sjj - e0;                          // even-aligned window start
    int cb = c0 + 24 - j;                       // bias column base

    for (int idx = tid; idx < NH*BH; idx += NT) {
        int hh = idx / BH, rem = idx - hh*BH;
        int rr = rem / RPBW, c = rem - rr*RPBW;
        int src = min(max(row_base + rr, 0), RPBW - 1);
        bias_s[idx] = rpb[hh*RPBW*RPBW + src*RPBW + c] * LOG2E;
    }

    // q vectors (broadcast-packed) + negated center scores (log2 units)
    float nsc[TR];
    ull qb2[TR][DH];
    #pragma unroll
    for (int t = 0; t < TR; ++t) {
        const float* qb = Q + ((size_t)(b*HT + i0 + t) * CC + h6) * WD + j;
        const float* kc = K + ((size_t)(b*HT + i0 + t) * CC + h6) * WD + j;
        float s = 0.f;
        #pragma unroll
        for (int d = 0; d < DH; ++d) {
            float qd = qb[d*WD];
            s = fmaf(qd, kc[d*WD], s);
            qb2[t][d] = bc2(qd);
        }
        nsc[t] = -s;
    }

    // edge masks (thread-constant)
    ull mfirst = pk2(e0 ? 0.f : 1.f, 1.f);
    ull mlast  = pk2(1.f, e0 ? 1.f : 0.f);

    ull accp[TR][DH], lp[TR];
    #pragma unroll
    for (int t = 0; t < TR; ++t) {
        lp[t] = 0ULL;
        #pragma unroll
        for (int d = 0; d < DH; ++d) accp[t][d] = 0ULL;
    }

    // prefetch first K row into registers; warm L1 with first V row
    float kr[6];
    {
        size_t rb = (size_t)(b*HT + r_lo) * CC * WD;
        #pragma unroll
        for (int u = 0; u < 6; ++u) kr[u] = K[rb + tid + u*NT];
        #pragma unroll
        for (int u = 0; u < 6; ++u) {
            float dmy;
            asm volatile("ld.global.nc.f32 %0, [%1];"
                         : "=f"(dmy) : "l"(V + rb + tid + u*NT));
        }
    }

    for (int rr = 0; rr < nrows; ++rr) {
        int r = r_lo + rr;
        float* kbuf = smem + 5684 + (rr & 1) * 2112;

        #pragma unroll
        for (int u = 0; u < 6; ++u) kbuf[tid + u*NT] = kr[u];
        __syncthreads();                        // single barrier per row

        if (rr + 1 < nrows) {                   // prefetch next K, warm next V
            size_t rb = (size_t)(b*HT + r + 1) * CC * WD;
            #pragma unroll
            for (int u = 0; u < 6; ++u) kr[u] = K[rb + tid + u*NT];
            #pragma unroll
            for (int u = 0; u < 6; ++u) {
                float dmy;
                asm volatile("ld.global.nc.f32 %0, [%1];"
                             : "=f"(dmy) : "l"(V + rb + tid + u*NT));
            }
        }

        // per-row shifts (row-validity kill, log2 units)
        ull shp[TR];
        shp[0] = bc2(nsc[0] + ((r <= sii[0] + 24) ? 0.f : -87.f));
        shp[1] = bc2(nsc[1] + ((r >= sii[1] && r <= sii[1] + 24) ? 0.f : -87.f));
        shp[2] = bc2(nsc[2] + ((r >= sii[2]) ? 0.f : -87.f));

        const float* kb = kbuf + h6*WD + c0;
        const ull*   vg = reinterpret_cast<const ull*>(
                            V + ((size_t)(b*HT + r) * CC + h6) * WD + c0);
        const float* br0 = bias_s + h*BH + (rr + 2)*RPBW + cb;  // query 0
        const float* br1 = br0 - RPBW;
        const float* br2 = br1 - RPBW;

        #pragma unroll
        for (int p = 0; p < 13; ++p) {
            ull kpair[DH], vpair[DH];
            #pragma unroll
            for (int d = 0; d < DH; ++d) {
                kpair[d] = lds64(kb + d*WD + 2*p);
                vpair[d] = vg[d*44 + p];        // LDG.64, 8B aligned
            }
            #pragma unroll
            for (int t = 0; t < TR; ++t) {
                const float* br = (t == 0) ? br0 : (t == 1) ? br1 : br2;
                ull s = add2(pk2(br[2*p], br[2*p + 1]), shp[t]);
                #pragma unroll
                for (int d = 0; d < DH; ++d) s = fma2(qb2[t][d], kpair[d], s);
                float s0, s1; upk2(s0, s1, s);
                ull pp = pk2(ex2f(s0), ex2f(s1));
                if (p == 0)  pp = mul2(pp, mfirst);
                if (p == 12) pp = mul2(pp, mlast);
                lp[t] = add2(lp[t], pp);
                #pragma unroll
                for (int d = 0; d < DH; ++d) accp[t][d] = fma2(pp, vpair[d], accp[t][d]);
            }
        }
    }

    // ---- epilogue ----------------------------------------------------------
    __syncthreads();
    float* attn_s = smem;                    // [3][88][25] = 6600
    const int NOUT = (MODE == 0) ? 72 : 24;
    float* ws = smem + 6600;                 // <=1728
    float* bs = smem + 8328;                 // <=72
    #pragma unroll
    for (int t = 0; t < TR; ++t) {
        float l0, l1; upk2(l0, l1, lp[t]);
        float inv = __fdividef(1.f, l0 + l1);
        #pragma unroll
        for (int d = 0; d < DH; ++d) {
            float a0, a1; upk2(a0, a1, accp[t][d]);
            attn_s[(t*WD + j)*25 + h6 + d] = (a0 + a1) * inv;
        }
    }
    for (int idx = tid; idx < CC*NOUT; idx += NT) ws[idx] = W[idx];
    for (int idx = tid; idx < NOUT; idx += NT) bs[idx] = bvec[idx];
    __syncthreads();

    if (MODE == 0) {
        #pragma unroll
        for (int pass = 0; pass < 3; ++pass) {
            int cf0 = h * 18 + pass * 6;
            float acc[TR][6];
            #pragma unroll
            for (int t = 0; t < TR; ++t)
                #pragma unroll
                for (int ci = 0; ci < 6; ++ci) acc[t][ci] = bs[cf0 + ci];
            #pragma unroll
            for (int u = 0; u < CC; ++u) {
                float wv[6], av[TR];
                #pragma unroll
                for (int ci = 0; ci < 6; ++ci) wv[ci] = ws[u*72 + cf0 + ci];
                #pragma unroll
                for (int t = 0; t < TR; ++t) av[t] = attn_s[(t*WD + j)*25 + u];
                #pragma unroll
                for (int t = 0; t < TR; ++t)
                    #pragma unroll
                    for (int ci = 0; ci < 6; ++ci)
                        acc[t][ci] = fmaf(av[t], wv[ci], acc[t][ci]);
            }
            int which = (cf0 >= 48) ? 2 : (cf0 >= 24 ? 1 : 0);
            int chb = cf0 - which * CC;
            float* dst = (which == 0) ? g_q2 : (which == 1) ? g_k2 : g_v2;
            #pragma unroll
            for (int t = 0; t < TR; ++t)
                #pragma unroll
                for (int ci = 0; ci < 6; ++ci)
                    dst[((size_t)(b*HT + i0 + t) * CC + chb + ci) * WD + j] = acc[t][ci];
        }
    } else {
        int cf0 = h * 6;
        float acc[TR][6];
        #pragma unroll
        for (int t = 0; t < TR; ++t)
            #pragma unroll
            for (int ci = 0; ci < 6; ++ci) acc[t][ci] = bs[cf0 + ci];
        #pragma unroll
        for (int u = 0; u < CC; ++u) {
            float wv[6], av[TR];
            #pragma unroll
            for (int ci = 0; ci < 6; ++ci) wv[ci] = ws[u*24 + cf0 + ci];
            #pragma unroll
            for (int t = 0; t < TR; ++t) av[t] = attn_s[(t*WD + j)*25 + u];
            #pragma unroll
            for (int t = 0; t < TR; ++t)
                #pragma unroll
                for (int ci = 0; ci < 6; ++ci)
                    acc[t][ci] = fmaf(av[t], wv[ci], acc[t][ci]);
        }
        __syncthreads();
        float* res_s = smem;                 // [3][88][24] = 6336
        #pragma unroll
        for (int t = 0; t < TR; ++t)
            #pragma unroll
            for (int ci = 0; ci < 6; ++ci)
                res_s[(t*WD + j)*CC + cf0 + ci] = acc[t][ci];
        __syncthreads();
        float* ob = outp + (size_t)(b*HT + i0) * WD * CC;
        for (int o = tid; o < TR*WD*CC; o += NT) ob[o] = res_s[o];
    }
}

// ---------------------------------------------------------------------------
extern "C" void kernel_launch(void* const* d_in, const int* in_sizes, int n_in,
                              void* d_out, int out_size) {
    (void)in_sizes; (void)n_in; (void)out_size;
    const float* x      = (const float*)d_in[0];
    const float* W_lin  = (const float*)d_in[1];
    const float* b_lin  = (const float*)d_in[2];
    const float* W_qkv  = (const float*)d_in[3];
    const float* b_qkv  = (const float*)d_in[4];
    const float* rpb    = (const float*)d_in[5];
    const float* W_proj = (const float*)d_in[6];
    const float* b_proj = (const float*)d_in[7];
    float* out = (float*)d_out;

    float *q, *k, *v, *q2, *k2, *v2, *wc, *bc;
    cudaGetSymbolAddress((void**)&q,  g_q);
    cudaGetSymbolAddress((void**)&k,  g_k);
    cudaGetSymbolAddress((void**)&v,  g_v);
    cudaGetSymbolAddress((void**)&q2, g_q2);
    cudaGetSymbolAddress((void**)&k2, g_k2);
    cudaGetSymbolAddress((void**)&v2, g_v2);
    cudaGetSymbolAddress((void**)&wc, g_wc);
    cudaGetSymbolAddress((void**)&bc, g_bc);

    k_comb<<<7, 256>>>(W_proj, b_proj, W_qkv, b_qkv);
    k_linqkv<<<BB*HT*2, 352>>>(x, W_lin, b_lin, W_qkv, b_qkv);
    k_attn<0><<<128, NT>>>(q,  k,  v,  rpb, wc,     bc,     nullptr);
    k_attn<1><<<128, NT>>>(q2, k2, v2, rpb, W_proj, b_proj, out);
}

// round 11
// speedup vs baseline: 1.1978x; 1.0330x over previous
#include <cuda_runtime.h>

// 0: x [2,192,88,133] f32, 1: W_lin [133,24], 2: b_lin [24], 3: W_qkv [24,72],
// 4: b_qkv [72], 5: rpb [4,49,49], 6: W_proj [24,24], 7: b_proj [24]
// output: [2,192,88,24] f32

#define BB   2
#define HT   192
#define WD   88
#define FIN  133
#define CC   24
#define NH   4
#define DH   6
#define WIN  25
#define NPIX (BB*HT*WD)   // 33792
#define NBI  (BB*HT)      // 384
#define RPBW 49
#define TR   3            // query rows per attn block
#define NT   352          // attn threads: 88 cols x 4 heads
#define BROWS 29
#define BH   (BROWS*RPBW) // 1421
#define LOG2E 1.4426950408889634f
#define NQ   44           // quads per (bi,ch)
#define BIAS_PAD 5696     // bias region padded to 16B multiple

typedef unsigned long long ull;

// Scratch (device globals: allocation-free). KV in quad-interleaved float4
// layout [bi][ch][44]{k0,k1,v0,v1} -> 16B-aligned LDG/STS/LDS.128.
__device__ float  g_q  [NPIX*CC];            // [bi][ch][col]
__device__ float  g_q2 [NPIX*CC];
__device__ float4 g_kv4 [NBI*CC*NQ];
__device__ float4 g_kv24[NBI*CC*NQ];
__device__ float  g_wc[CC*72], g_bc[72];

// ---- packed f32x2 helpers --------------------------------------------------
__device__ __forceinline__ ull pk2(float lo, float hi) {
    ull r; asm("mov.b64 %0, {%1,%2};" : "=l"(r) : "f"(lo), "f"(hi)); return r;
}
__device__ __forceinline__ ull bc2(float v) { return pk2(v, v); }
__device__ __forceinline__ void upk2(float& lo, float& hi, ull v) {
    asm("mov.b64 {%0,%1}, %2;" : "=f"(lo), "=f"(hi) : "l"(v));
}
__device__ __forceinline__ ull fma2(ull a, ull b, ull c) {
    ull d; asm("fma.rn.f32x2 %0, %1, %2, %3;" : "=l"(d) : "l"(a), "l"(b), "l"(c)); return d;
}
__device__ __forceinline__ ull add2(ull a, ull b) {
    ull d; asm("add.rn.f32x2 %0, %1, %2;" : "=l"(d) : "l"(a), "l"(b)); return d;
}
__device__ __forceinline__ ull mul2(ull a, ull b) {
    ull d; asm("mul.rn.f32x2 %0, %1, %2;" : "=l"(d) : "l"(a), "l"(b)); return d;
}
__device__ __forceinline__ float ex2f(float x) {
    float y; asm("ex2.approx.f32 %0, %1;" : "=f"(y) : "f"(x)); return y;
}

// ---------------------------------------------------------------------------
// Setup: Wcomb = W_proj @ W_qkv, bcomb = b_proj @ W_qkv + b_qkv
// (q columns scaled by dh^-0.5 * log2(e) for raw ex2 in attention)
// ---------------------------------------------------------------------------
__global__ void k_comb(const float* __restrict__ Wp, const float* __restrict__ bp,
                       const float* __restrict__ Wq, const float* __restrict__ bq) {
    int t = blockIdx.x * blockDim.x + threadIdx.x;
    const float QS = 0.40824829046386302f * LOG2E;
    if (t < CC*72) {
        int u = t / 72, cf = t % 72;
        float a = 0.f;
        #pragma unroll
        for (int w = 0; w < CC; ++w) a = fmaf(Wp[u*CC + w], Wq[w*72 + cf], a);
        if (cf < CC) a *= QS;
        g_wc[t] = a;
    }
    if (t < 72) {
        float a = bq[t];
        #pragma unroll
        for (int w = 0; w < CC; ++w) a = fmaf(bp[w], Wq[w*72 + t], a);
        if (t < CC) a *= QS;
        g_bc[t] = a;
    }
}

// ---------------------------------------------------------------------------
// Fused linear+ReLU+qkv: block = 44-pixel half row. q -> g_q, k/v -> g_kv4.
// ---------------------------------------------------------------------------
__global__ void __launch_bounds__(352) k_linqkv(const float* __restrict__ x,
                                                const float* __restrict__ Wl,
                                                const float* __restrict__ bl,
                                                const float* __restrict__ Wq,
                                                const float* __restrict__ bq) {
    __shared__ float sm[11872];
    float* xs = sm;               // 44*133 = 5852
    float* wl = sm + 5852;        // 133*24 = 3192
    float* hs = sm + 9044;        // 44*25  = 1100
    float* wq = sm + 10144;       // 24*72  = 1728

    int blk = blockIdx.x;
    int bi = blk >> 1, jb = (blk & 1) * 44;
    int tid = threadIdx.x;

    const float* xb = x + ((size_t)bi * WD + jb) * FIN;
    for (int idx = tid; idx < 44*FIN; idx += 352) xs[idx] = xb[idx];
    for (int idx = tid; idx < FIN*CC; idx += 352) wl[idx] = Wl[idx];
    for (int idx = tid; idx < CC*72; idx += 352) wq[idx] = Wq[idx];
    __syncthreads();

    int jl = tid % 44, cg = tid / 44;      // cg in [0,8): 3 channels each
    int c0 = cg * 3;
    float acc[3];
    #pragma unroll
    for (int i = 0; i < 3; ++i) acc[i] = bl[c0 + i];
    #pragma unroll 7
    for (int f = 0; f < FIN; ++f) {
        float xf = xs[jl*FIN + f];
        #pragma unroll
        for (int i = 0; i < 3; ++i) acc[i] = fmaf(xf, wl[f*CC + c0 + i], acc[i]);
    }
    #pragma unroll
    for (int i = 0; i < 3; ++i) hs[jl*25 + c0 + i] = fmaxf(acc[i], 0.f);
    __syncthreads();

    const float QS = 0.40824829046386302f * LOG2E;
    float* kvf = reinterpret_cast<float*>(g_kv4);
    for (int o = tid; o < 44*72; o += 352) {
        int cf = o / 44, j2 = o - cf*44;
        float a = bq[cf];
        #pragma unroll
        for (int u = 0; u < CC; ++u) a = fmaf(hs[j2*25 + u], wq[u*72 + cf], a);
        int which = cf / CC, ch = cf % CC;
        int j = jb + j2;
        if (which == 0) {
            g_q[((size_t)bi * CC + ch) * WD + j] = a * QS;
        } else {
            kvf[(((size_t)bi * CC + ch) * NQ + (j >> 1)) * 4 + (j & 1)
                + (which == 2 ? 2 : 0)] = a;
        }
    }
}

// ---------------------------------------------------------------------------
// Attention (TR=3, 352 thr, grid 128): K+V staged together as 16B quads
// (3 LDG.128 + 3 STS.128 per thread per row), consumed as LDS.128 ->
// ulonglong2 whose halves ARE the f32x2 operands. Split-dot score chains,
// log2-domain scores, raw ex2. Lane pairs share quad addresses (broadcast).
// MODE 0: epilogue -> layer-2 q/kv via Wcomb. MODE 1: final projection.
// ---------------------------------------------------------------------------
template<int MODE>
__global__ void __launch_bounds__(NT, 1) k_attn(
    const float* __restrict__ Q, const float4* __restrict__ KV,
    const float* __restrict__ rpb,
    const float* __restrict__ W, const float* __restrict__ bvec,
    float* __restrict__ outp)
{
    __shared__ __align__(16) float smem[BIAS_PAD + CC*NQ*4];   // 5696+4224
    float* bias_s = smem;           // 5684 used (scaled by log2e)

    int blk = blockIdx.x;           // 128 blocks
    int b = blk >> 6, it = blk & 63;
    int i0 = it * TR;
    int tid = threadIdx.x;
    int j = tid % WD, h = tid / WD, h6 = h * DH;

    int sii[TR];
    #pragma unroll
    for (int t = 0; t < TR; ++t) sii[t] = min(max(i0 + t - 12, 0), HT - WIN);
    int r_lo = sii[0];
    int nrows = sii[2] + WIN - r_lo;           // 25..27
    int row_base = r_lo - i0 + 22;

    int sjj = min(max(j - 12, 0), WD - WIN);
    int e0 = sjj & 1;
    int c0 = sjj - e0;                          // even-aligned window start
    int qb0 = c0 >> 1;                          // quad base [0,31]
    int cb = c0 + 24 - j;                       // bias column base

    for (int idx = tid; idx < NH*BH; idx += NT) {
        int hh = idx / BH, rem = idx - hh*BH;
        int rr = rem / RPBW, c = rem - rr*RPBW;
        int src = min(max(row_base + rr, 0), RPBW - 1);
        bias_s[idx] = rpb[hh*RPBW*RPBW + src*RPBW + c] * LOG2E;
    }

    // q vectors (broadcast-packed) + negated center scores (log2 units)
    float nsc[TR];
    ull qv2[TR][DH];
    const float* KVf = reinterpret_cast<const float*>(KV);
    #pragma unroll
    for (int t = 0; t < TR; ++t) {
        const float* qp = Q + ((size_t)(b*HT + i0 + t) * CC + h6) * WD + j;
        size_t kcq = (((size_t)(b*HT + i0 + t) * CC + h6) * NQ + (j >> 1)) * 4 + (j & 1);
        float s = 0.f;
        #pragma unroll
        for (int d = 0; d < DH; ++d) {
            float qd = qp[d*WD];
            s = fmaf(qd, KVf[kcq + (size_t)d*NQ*4], s);
            qv2[t][d] = bc2(qd);
        }
        nsc[t] = -s;
    }

    // edge masks (thread-constant)
    ull mfirst = pk2(e0 ? 0.f : 1.f, 1.f);
    ull mlast  = pk2(1.f, e0 ? 1.f : 0.f);

    ull accp[TR][DH], lp[TR];
    #pragma unroll
    for (int t = 0; t < TR; ++t) {
        lp[t] = 0ULL;
        #pragma unroll
        for (int d = 0; d < DH; ++d) accp[t][d] = 0ULL;
    }

    float4* sbuf = reinterpret_cast<float4*>(smem + BIAS_PAD);

    // prefetch first row's quads (3 per thread)
    float4 kvr[3];
    {
        const float4* src = KV + (size_t)(b*HT + r_lo) * CC * NQ;
        #pragma unroll
        for (int u = 0; u < 3; ++u) kvr[u] = src[tid + u*NT];
    }

    for (int rr = 0; rr < nrows; ++rr) {
        int r = r_lo + rr;
        __syncthreads();
        #pragma unroll
        for (int u = 0; u < 3; ++u) sbuf[tid + u*NT] = kvr[u];
        __syncthreads();
        if (rr + 1 < nrows) {
            const float4* src = KV + (size_t)(b*HT + r + 1) * CC * NQ;
            #pragma unroll
            for (int u = 0; u < 3; ++u) kvr[u] = src[tid + u*NT];
        }

        // per-row shifts (row-validity kill, log2 units)
        ull shp[TR];
        shp[0] = bc2(nsc[0] + ((r <= sii[0] + 24) ? 0.f : -87.f));
        shp[1] = bc2(nsc[1] + ((r >= sii[1] && r <= sii[1] + 24) ? 0.f : -87.f));
        shp[2] = bc2(nsc[2] + ((r >= sii[2]) ? 0.f : -87.f));

        const ulonglong2* kvp = reinterpret_cast<const ulonglong2*>(sbuf)
                                + h6*NQ + qb0;
        const float* br0 = bias_s + h*BH + (rr + 2)*RPBW + cb;  // query 0
        const float* br1 = br0 - RPBW;
        const float* br2 = br1 - RPBW;

        #pragma unroll
        for (int p = 0; p < 13; ++p) {
            ull kpair[DH], vpair[DH];
            #pragma unroll
            for (int d = 0; d < DH; ++d) {
                ulonglong2 u2 = kvp[d*NQ + p];   // LDS.128: {k0,k1},{v0,v1}
                kpair[d] = u2.x;
                vpair[d] = u2.y;
            }
            #pragma unroll
            for (int t = 0; t < TR; ++t) {
                const float* br = (t == 0) ? br0 : (t == 1) ? br1 : br2;
                // split-dot: two 3-chains
                ull sA = add2(pk2(br[2*p], br[2*p + 1]), shp[t]);
                #pragma unroll
                for (int d = 0; d < 3; ++d) sA = fma2(qv2[t][d], kpair[d], sA);
                ull sB = mul2(qv2[t][3], kpair[3]);
                sB = fma2(qv2[t][4], kpair[4], sB);
                sB = fma2(qv2[t][5], kpair[5], sB);
                float s0, s1; upk2(s0, s1, add2(sA, sB));
                ull pp = pk2(ex2f(s0), ex2f(s1));
                if (p == 0)  pp = mul2(pp, mfirst);
                if (p == 12) pp = mul2(pp, mlast);
                lp[t] = add2(lp[t], pp);
                #pragma unroll
                for (int d = 0; d < DH; ++d) accp[t][d] = fma2(pp, vpair[d], accp[t][d]);
            }
        }
    }

    // ---- epilogue ----------------------------------------------------------
    __syncthreads();
    float* attn_s = smem;                    // [3][88][25] = 6600
    const int NOUT = (MODE == 0) ? 72 : 24;
    float* ws = smem + 6600;                 // <=1728
    float* bs = smem + 8328;                 // <=72
    #pragma unroll
    for (int t = 0; t < TR; ++t) {
        float l0, l1; upk2(l0, l1, lp[t]);
        float inv = __fdividef(1.f, l0 + l1);
        #pragma unroll
        for (int d = 0; d < DH; ++d) {
            float a0, a1; upk2(a0, a1, accp[t][d]);
            attn_s[(t*WD + j)*25 + h6 + d] = (a0 + a1) * inv;
        }
    }
    for (int idx = tid; idx < CC*NOUT; idx += NT) ws[idx] = W[idx];
    for (int idx = tid; idx < NOUT; idx += NT) bs[idx] = bvec[idx];
    __syncthreads();

    if (MODE == 0) {
        float* kvo = reinterpret_cast<float*>(g_kv24);
        #pragma unroll
        for (int pass = 0; pass < 3; ++pass) {
            int cf0 = h * 18 + pass * 6;
            float acc[TR][6];
            #pragma unroll
            for (int t = 0; t < TR; ++t)
                #pragma unroll
                for (int ci = 0; ci < 6; ++ci) acc[t][ci] = bs[cf0 + ci];
            #pragma unroll
            for (int u = 0; u < CC; ++u) {
                float wv[6], av[TR];
                #pragma unroll
                for (int ci = 0; ci < 6; ++ci) wv[ci] = ws[u*72 + cf0 + ci];
                #pragma unroll
                for (int t = 0; t < TR; ++t) av[t] = attn_s[(t*WD + j)*25 + u];
                #pragma unroll
                for (int t = 0; t < TR; ++t)
                    #pragma unroll
                    for (int ci = 0; ci < 6; ++ci)
                        acc[t][ci] = fmaf(av[t], wv[ci], acc[t][ci]);
            }
            int which = (cf0 >= 48) ? 2 : (cf0 >= 24 ? 1 : 0);
            int chb = cf0 - which * CC;
            #pragma unroll
            for (int t = 0; t < TR; ++t) {
                size_t bi_t = (size_t)(b*HT + i0 + t);
                #pragma unroll
                for (int ci = 0; ci < 6; ++ci) {
                    if (which == 0)
                        g_q2[(bi_t * CC + chb + ci) * WD + j] = acc[t][ci];
                    else
                        kvo[((bi_t * CC + chb + ci) * NQ + (j >> 1)) * 4
                            + (j & 1) + (which == 2 ? 2 : 0)] = acc[t][ci];
                }
            }
        }
    } else {
        int cf0 = h * 6;
        float acc[TR][6];
        #pragma unroll
        for (int t = 0; t < TR; ++t)
            #pragma unroll
            for (int ci = 0; ci < 6; ++ci) acc[t][ci] = bs[cf0 + ci];
        #pragma unroll
        for (int u = 0; u < CC; ++u) {
            float wv[6], av[TR];
            #pragma unroll
            for (int ci = 0; ci < 6; ++ci) wv[ci] = ws[u*24 + cf0 + ci];
            #pragma unroll
            for (int t = 0; t < TR; ++t) av[t] = attn_s[(t*WD + j)*25 + u];
            #pragma unroll
            for (int t = 0; t < TR; ++t)
                #pragma unroll
                for (int ci = 0; ci < 6; ++ci)
                    acc[t][ci] = fmaf(av[t], wv[ci], acc[t][ci]);
        }
        __syncthreads();
        float* res_s = smem;                 // [3][88][24] = 6336
        #pragma unroll
        for (int t = 0; t < TR; ++t)
            #pragma unroll
            for (int ci = 0; ci < 6; ++ci)
                res_s[(t*WD + j)*CC + cf0 + ci] = acc[t][ci];
        __syncthreads();
        float* ob = outp + (size_t)(b*HT + i0) * WD * CC;
        for (int o = tid; o < TR*WD*CC; o += NT) ob[o] = res_s[o];
    }
}

// ---------------------------------------------------------------------------
extern "C" void kernel_launch(void* const* d_in, const int* in_sizes, int n_in,
                              void* d_out, int out_size) {
    (void)in_sizes; (void)n_in; (void)out_size;
    const float* x      = (const float*)d_in[0];
    const float* W_lin  = (const float*)d_in[1];
    const float* b_lin  = (const float*)d_in[2];
    const float* W_qkv  = (const float*)d_in[3];
    const float* b_qkv  = (const float*)d_in[4];
    const float* rpb    = (const float*)d_in[5];
    const float* W_proj = (const float*)d_in[6];
    const float* b_proj = (const float*)d_in[7];
    float* out = (float*)d_out;

    float *q, *q2, *wc, *bc;
    float4 *kv, *kv2;
    cudaGetSymbolAddress((void**)&q,   g_q);
    cudaGetSymbolAddress((void**)&q2,  g_q2);
    cudaGetSymbolAddress((void**)&kv,  g_kv4);
    cudaGetSymbolAddress((void**)&kv2, g_kv24);
    cudaGetSymbolAddress((void**)&wc,  g_wc);
    cudaGetSymbolAddress((void**)&bc,  g_bc);

    k_comb<<<7, 256>>>(W_proj, b_proj, W_qkv, b_qkv);
    k_linqkv<<<BB*HT*2, 352>>>(x, W_lin, b_lin, W_qkv, b_qkv);
    k_attn<0><<<128, NT>>>(q,  kv,  rpb, wc,     bc,     nullptr);
    k_attn<1><<<128, NT>>>(q2, kv2, rpb, W_proj, b_proj, out);
}

// round 14
// speedup vs baseline: 1.2604x; 1.0522x over previous
#include <cuda_runtime.h>

// 0: x [2,192,88,133] f32, 1: W_lin [133,24], 2: b_lin [24], 3: W_qkv [24,72],
// 4: b_qkv [72], 5: rpb [4,49,49], 6: W_proj [24,24], 7: b_proj [24]
// output: [2,192,88,24] f32

#define BB   2
#define HT   192
#define WD   88
#define FIN  133
#define CC   24
#define NH   4
#define DH   6
#define WIN  25
#define NPIX (BB*HT*WD)   // 33792
#define NBI  (BB*HT)      // 384
#define RPBW 49
#define TR   3            // query rows per attn block
#define NT   352          // attn threads: 88 cols x 4 heads
#define BROWS 29
#define BH   (BROWS*RPBW) // 1421
#define LOG2E 1.4426950408889634f
#define NQ   44           // quads per (bi,ch)
#define BIAS_PAD 5696     // bias region padded to 16B multiple

typedef unsigned long long ull;

// Scratch (device globals: allocation-free). KV in quad-interleaved float4
// layout [bi][ch][44]{k0,k1,v0,v1} -> 16B-aligned LDG/STS/LDS.128.
__device__ float  g_q  [NPIX*CC];            // [bi][ch][col]
__device__ float  g_q2 [NPIX*CC];
__device__ float4 g_kv4 [NBI*CC*NQ];
__device__ float4 g_kv24[NBI*CC*NQ];
__device__ float  g_wc[CC*72], g_bc[72];

// ---- packed f32x2 helpers --------------------------------------------------
__device__ __forceinline__ ull pk2(float lo, float hi) {
    ull r; asm("mov.b64 %0, {%1,%2};" : "=l"(r) : "f"(lo), "f"(hi)); return r;
}
__device__ __forceinline__ ull bc2(float v) { return pk2(v, v); }
__device__ __forceinline__ void upk2(float& lo, float& hi, ull v) {
    asm("mov.b64 {%0,%1}, %2;" : "=f"(lo), "=f"(hi) : "l"(v));
}
__device__ __forceinline__ ull fma2(ull a, ull b, ull c) {
    ull d; asm("fma.rn.f32x2 %0, %1, %2, %3;" : "=l"(d) : "l"(a), "l"(b), "l"(c)); return d;
}
__device__ __forceinline__ ull add2(ull a, ull b) {
    ull d; asm("add.rn.f32x2 %0, %1, %2;" : "=l"(d) : "l"(a), "l"(b)); return d;
}
__device__ __forceinline__ ull mul2(ull a, ull b) {
    ull d; asm("mul.rn.f32x2 %0, %1, %2;" : "=l"(d) : "l"(a), "l"(b)); return d;
}
__device__ __forceinline__ float ex2f(float x) {
    float y; asm("ex2.approx.f32 %0, %1;" : "=f"(y) : "f"(x)); return y;
}
__device__ __forceinline__ ull lds64(const float* p) {
    return *reinterpret_cast<const ull*>(p);   // even float offset from 16B base
}

// ---------------------------------------------------------------------------
// Setup: Wcomb = W_proj @ W_qkv, bcomb = b_proj @ W_qkv + b_qkv
// (q columns scaled by dh^-0.5 * log2(e) for raw ex2 in attention)
// ---------------------------------------------------------------------------
__global__ void k_comb(const float* __restrict__ Wp, const float* __restrict__ bp,
                       const float* __restrict__ Wq, const float* __restrict__ bq) {
    int t = blockIdx.x * blockDim.x + threadIdx.x;
    const float QS = 0.40824829046386302f * LOG2E;
    if (t < CC*72) {
        int u = t / 72, cf = t % 72;
        float a = 0.f;
        #pragma unroll
        for (int w = 0; w < CC; ++w) a = fmaf(Wp[u*CC + w], Wq[w*72 + cf], a);
        if (cf < CC) a *= QS;
        g_wc[t] = a;
    }
    if (t < 72) {
        float a = bq[t];
        #pragma unroll
        for (int w = 0; w < CC; ++w) a = fmaf(bp[w], Wq[w*72 + t], a);
        if (t < CC) a *= QS;
        g_bc[t] = a;
    }
}

// ---------------------------------------------------------------------------
// Fused linear+ReLU+qkv, f32x2-packed: block = 44-pixel half row.
// Weights staged TRANSPOSED with even strides so both operands of each
// packed FMA come from LDS.64. q -> g_q, k/v -> g_kv4 (quad-interleaved).
// ---------------------------------------------------------------------------
#define XS_STR 134            // xs row stride (even)
#define WL_STR 134            // wlT row stride (even)
#define HS_STR 26             // hs row stride (even)
#define WQ_STR 26             // wqT row stride (even)

__global__ void __launch_bounds__(352) k_linqkv(const float* __restrict__ x,
                                                const float* __restrict__ Wl,
                                                const float* __restrict__ bl,
                                                const float* __restrict__ Wq,
                                                const float* __restrict__ bq) {
    __shared__ __align__(16) float sm[12128];
    float* xs  = sm;                       // 44*134 = 5896
    float* wlT = sm + 5896;                // 24*134 = 3216 (wlT[c][f])
    float* hs  = sm + 9112;                // 44*26  = 1144
    float* wqT = sm + 10256;               // 72*26  = 1872 (wqT[cf][u])

    int blk = blockIdx.x;
    int bi = blk >> 1, jb = (blk & 1) * 44;
    int tid = threadIdx.x;

    const float* xb = x + ((size_t)bi * WD + jb) * FIN;
    for (int idx = tid; idx < 44*FIN; idx += 352)
        xs[(idx / FIN) * XS_STR + (idx % FIN)] = xb[idx];
    for (int idx = tid; idx < FIN*CC; idx += 352)      // transpose W_lin
        wlT[(idx % CC) * WL_STR + (idx / CC)] = Wl[idx];
    for (int idx = tid; idx < CC*72; idx += 352)       // transpose W_qkv
        wqT[(idx % 72) * WQ_STR + (idx / 72)] = Wq[idx];
    __syncthreads();

    // Phase A: h = relu(x @ W_lin + b_lin), packed over f-pairs
    int jl = tid % 44, cg = tid / 44;      // cg in [0,8): 3 channels each
    int c0 = cg * 3;
    ull acc2[3];
    float accs[3];
    #pragma unroll
    for (int i = 0; i < 3; ++i) { acc2[i] = 0ULL; accs[i] = bl[c0 + i]; }

    const float* xrow = xs + jl * XS_STR;
    #pragma unroll 6
    for (int fp = 0; fp < 66; ++fp) {
        ull xp = lds64(xrow + 2*fp);
        #pragma unroll
        for (int i = 0; i < 3; ++i)
            acc2[i] = fma2(xp, lds64(wlT + (c0 + i)*WL_STR + 2*fp), acc2[i]);
    }
    {   // tail f = 132
        float xf = xrow[132];
        #pragma unroll
        for (int i = 0; i < 3; ++i)
            accs[i] = fmaf(xf, wlT[(c0 + i)*WL_STR + 132], accs[i]);
    }
    #pragma unroll
    for (int i = 0; i < 3; ++i) {
        float lo, hi; upk2(lo, hi, acc2[i]);
        hs[jl*HS_STR + c0 + i] = fmaxf(lo + hi + accs[i], 0.f);
    }
    __syncthreads();

    // Phase B: qkv = h @ W_qkv + b_qkv, packed over u-pairs (12 exact)
    const float QS = 0.40824829046386302f * LOG2E;
    float* kvf = reinterpret_cast<float*>(g_kv4);
    for (int o = tid; o < 44*72; o += 352) {
        int cf = o / 44, j2 = o - cf*44;
        ull a2 = 0ULL;
        const float* hrow = hs + j2 * HS_STR;
        const float* wrow = wqT + cf * WQ_STR;
        #pragma unroll
        for (int up = 0; up < 12; ++up)
            a2 = fma2(lds64(hrow + 2*up), lds64(wrow + 2*up), a2);
        float lo, hi; upk2(lo, hi, a2);
        float a = lo + hi + bq[cf];
        int which = cf / CC, ch = cf % CC;
        int j = jb + j2;
        if (which == 0) {
            g_q[((size_t)bi * CC + ch) * WD + j] = a * QS;
        } else {
            kvf[(((size_t)bi * CC + ch) * NQ + (j >> 1)) * 4 + (j & 1)
                + (which == 2 ? 2 : 0)] = a;
        }
    }
}

// ---------------------------------------------------------------------------
// Attention (TR=3, 352 thr, grid 128): K+V staged together as 16B quads
// (3 LDG.128 + 3 STS.128 per thread per row), consumed as LDS.128 ->
// ulonglong2 whose halves ARE the f32x2 operands. Split-dot score chains,
// log2-domain scores, raw ex2. Lane pairs share quad addresses (broadcast).
// MODE 0: epilogue -> layer-2 q/kv via Wcomb. MODE 1: final projection.
// ---------------------------------------------------------------------------
template<int MODE>
__global__ void __launch_bounds__(NT, 1) k_attn(
    const float* __restrict__ Q, const float4* __restrict__ KV,
    const float* __restrict__ rpb,
    const float* __restrict__ W, const float* __restrict__ bvec,
    float* __restrict__ outp)
{
    __shared__ __align__(16) float smem[BIAS_PAD + CC*NQ*4];   // 5696+4224
    float* bias_s = smem;           // 5684 used (scaled by log2e)

    int blk = blockIdx.x;           // 128 blocks
    int b = blk >> 6, it = blk & 63;
    int i0 = it * TR;
    int tid = threadIdx.x;
    int j = tid % WD, h = tid / WD, h6 = h * DH;

    int sii[TR];
    #pragma unroll
    for (int t = 0; t < TR; ++t) sii[t] = min(max(i0 + t - 12, 0), HT - WIN);
    int r_lo = sii[0];
    int nrows = sii[2] + WIN - r_lo;           // 25..27
    int row_base = r_lo - i0 + 22;

    int sjj = min(max(j - 12, 0), WD - WIN);
    int e0 = sjj & 1;
    int c0 = sjj - e0;                          // even-aligned window start
    int qb0 = c0 >> 1;                          // quad base [0,31]
    int cb = c0 + 24 - j;                       // bias column base

    for (int idx = tid; idx < NH*BH; idx += NT) {
        int hh = idx / BH, rem = idx - hh*BH;
        int rr = rem / RPBW, c = rem - rr*RPBW;
        int src = min(max(row_base + rr, 0), RPBW - 1);
        bias_s[idx] = rpb[hh*RPBW*RPBW + src*RPBW + c] * LOG2E;
    }

    // q vectors (broadcast-packed) + negated center scores (log2 units)
    float nsc[TR];
    ull qv2[TR][DH];
    const float* KVf = reinterpret_cast<const float*>(KV);
    #pragma unroll
    for (int t = 0; t < TR; ++t) {
        const float* qp = Q + ((size_t)(b*HT + i0 + t) * CC + h6) * WD + j;
        size_t kcq = (((size_t)(b*HT + i0 + t) * CC + h6) * NQ + (j >> 1)) * 4 + (j & 1);
        float s = 0.f;
        #pragma unroll
        for (int d = 0; d < DH; ++d) {
            float qd = qp[d*WD];
            s = fmaf(qd, KVf[kcq + (size_t)d*NQ*4], s);
            qv2[t][d] = bc2(qd);
        }
        nsc[t] = -s;
    }

    // edge masks (thread-constant)
    ull mfirst = pk2(e0 ? 0.f : 1.f, 1.f);
    ull mlast  = pk2(1.f, e0 ? 1.f : 0.f);

    ull accp[TR][DH], lp[TR];
    #pragma unroll
    for (int t = 0; t < TR; ++t) {
        lp[t] = 0ULL;
        #pragma unroll
        for (int d = 0; d < DH; ++d) accp[t][d] = 0ULL;
    }

    float4* sbuf = reinterpret_cast<float4*>(smem + BIAS_PAD);

    // prefetch first row's quads (3 per thread)
    float4 kvr[3];
    {
        const float4* src = KV + (size_t)(b*HT + r_lo) * CC * NQ;
        #pragma unroll
        for (int u = 0; u < 3; ++u) kvr[u] = src[tid + u*NT];
    }

    for (int rr = 0; rr < nrows; ++rr) {
        int r = r_lo + rr;
        __syncthreads();
        #pragma unroll
        for (int u = 0; u < 3; ++u) sbuf[tid + u*NT] = kvr[u];
        __syncthreads();
        if (rr + 1 < nrows) {
            const float4* src = KV + (size_t)(b*HT + r + 1) * CC * NQ;
            #pragma unroll
            for (int u = 0; u < 3; ++u) kvr[u] = src[tid + u*NT];
        }

        // per-row shifts (row-validity kill, log2 units)
        ull shp[TR];
        shp[0] = bc2(nsc[0] + ((r <= sii[0] + 24) ? 0.f : -87.f));
        shp[1] = bc2(nsc[1] + ((r >= sii[1] && r <= sii[1] + 24) ? 0.f : -87.f));
        shp[2] = bc2(nsc[2] + ((r >= sii[2]) ? 0.f : -87.f));

        const ulonglong2* kvp = reinterpret_cast<const ulonglong2*>(sbuf)
                                + h6*NQ + qb0;
        const float* br0 = bias_s + h*BH + (rr + 2)*RPBW + cb;  // query 0
        const float* br1 = br0 - RPBW;
        const float* br2 = br1 - RPBW;

        #pragma unroll
        for (int p = 0; p < 13; ++p) {
            ull kpair[DH], vpair[DH];
            #pragma unroll
            for (int d = 0; d < DH; ++d) {
                ulonglong2 u2 = kvp[d*NQ + p];   // LDS.128: {k0,k1},{v0,v1}
                kpair[d] = u2.x;
                vpair[d] = u2.y;
            }
            #pragma unroll
            for (int t = 0; t < TR; ++t) {
                const float* br = (t == 0) ? br0 : (t == 1) ? br1 : br2;
                // split-dot: two 3-chains
                ull sA = add2(pk2(br[2*p], br[2*p + 1]), shp[t]);
                #pragma unroll
                for (int d = 0; d < 3; ++d) sA = fma2(qv2[t][d], kpair[d], sA);
                ull sB = mul2(qv2[t][3], kpair[3]);
                sB = fma2(qv2[t][4], kpair[4], sB);
                sB = fma2(qv2[t][5], kpair[5], sB);
                float s0, s1; upk2(s0, s1, add2(sA, sB));
                ull pp = pk2(ex2f(s0), ex2f(s1));
                if (p == 0)  pp = mul2(pp, mfirst);
                if (p == 12) pp = mul2(pp, mlast);
                lp[t] = add2(lp[t], pp);
                #pragma unroll
                for (int d = 0; d < DH; ++d) accp[t][d] = fma2(pp, vpair[d], accp[t][d]);
            }
        }
    }

    // ---- epilogue ----------------------------------------------------------
    __syncthreads();
    float* attn_s = smem;                    // [3][88][25] = 6600
    const int NOUT = (MODE == 0) ? 72 : 24;
    float* ws = smem + 6600;                 // <=1728
    float* bs = smem + 8328;                 // <=72
    #pragma unroll
    for (int t = 0; t < TR; ++t) {
        float l0, l1; upk2(l0, l1, lp[t]);
        float inv = __fdividef(1.f, l0 + l1);
        #pragma unroll
        for (int d = 0; d < DH; ++d) {
            float a0, a1; upk2(a0, a1, accp[t][d]);
            attn_s[(t*WD + j)*25 + h6 + d] = (a0 + a1) * inv;
        }
    }
    for (int idx = tid; idx < CC*NOUT; idx += NT) ws[idx] = W[idx];
    for (int idx = tid; idx < NOUT; idx += NT) bs[idx] = bvec[idx];
    __syncthreads();

    if (MODE == 0) {
        float* kvo = reinterpret_cast<float*>(g_kv24);
        #pragma unroll
        for (int pass = 0; pass < 3; ++pass) {
            int cf0 = h * 18 + pass * 6;
            float acc[TR][6];
            #pragma unroll
            for (int t = 0; t < TR; ++t)
                #pragma unroll
                for (int ci = 0; ci < 6; ++ci) acc[t][ci] = bs[cf0 + ci];
            #pragma unroll
            for (int u = 0; u < CC; ++u) {
                float wv[6], av[TR];
                #pragma unroll
                for (int ci = 0; ci < 6; ++ci) wv[ci] = ws[u*72 + cf0 + ci];
                #pragma unroll
                for (int t = 0; t < TR; ++t) av[t] = attn_s[(t*WD + j)*25 + u];
                #pragma unroll
                for (int t = 0; t < TR; ++t)
                    #pragma unroll
                    for (int ci = 0; ci < 6; ++ci)
                        acc[t][ci] = fmaf(av[t], wv[ci], acc[t][ci]);
            }
            int which = (cf0 >= 48) ? 2 : (cf0 >= 24 ? 1 : 0);
            int chb = cf0 - which * CC;
            #pragma unroll
            for (int t = 0; t < TR; ++t) {
                size_t bi_t = (size_t)(b*HT + i0 + t);
                #pragma unroll
                for (int ci = 0; ci < 6; ++ci) {
                    if (which == 0)
                        g_q2[(bi_t * CC + chb + ci) * WD + j] = acc[t][ci];
                    else
                        kvo[((bi_t * CC + chb + ci) * NQ + (j >> 1)) * 4
                            + (j & 1) + (which == 2 ? 2 : 0)] = acc[t][ci];
                }
            }
        }
    } else {
        int cf0 = h * 6;
        float acc[TR][6];
        #pragma unroll
        for (int t = 0; t < TR; ++t)
            #pragma unroll
            for (int ci = 0; ci < 6; ++ci) acc[t][ci] = bs[cf0 + ci];
        #pragma unroll
        for (int u = 0; u < CC; ++u) {
            float wv[6], av[TR];
            #pragma unroll
            for (int ci = 0; ci < 6; ++ci) wv[ci] = ws[u*24 + cf0 + ci];
            #pragma unroll
            for (int t = 0; t < TR; ++t) av[t] = attn_s[(t*WD + j)*25 + u];
            #pragma unroll
            for (int t = 0; t < TR; ++t)
                #pragma unroll
                for (int ci = 0; ci < 6; ++ci)
                    acc[t][ci] = fmaf(av[t], wv[ci], acc[t][ci]);
        }
        __syncthreads();
        float* res_s = smem;                 // [3][88][24] = 6336
        #pragma unroll
        for (int t = 0; t < TR; ++t)
            #pragma unroll
            for (int ci = 0; ci < 6; ++ci)
                res_s[(t*WD + j)*CC + cf0 + ci] = acc[t][ci];
        __syncthreads();
        float* ob = outp + (size_t)(b*HT + i0) * WD * CC;
        for (int o = tid; o < TR*WD*CC; o += NT) ob[o] = res_s[o];
    }
}

// ---------------------------------------------------------------------------
extern "C" void kernel_launch(void* const* d_in, const int* in_sizes, int n_in,
                              void* d_out, int out_size) {
    (void)in_sizes; (void)n_in; (void)out_size;
    const float* x      = (const float*)d_in[0];
    const float* W_lin  = (const float*)d_in[1];
    const float* b_lin  = (const float*)d_in[2];
    const float* W_qkv  = (const float*)d_in[3];
    const float* b_qkv  = (const float*)d_in[4];
    const float* rpb    = (const float*)d_in[5];
    const float* W_proj = (const float*)d_in[6];
    const float* b_proj = (const float*)d_in[7];
    float* out = (float*)d_out;

    float *q, *q2, *wc, *bc;
    float4 *kv, *kv2;
    cudaGetSymbolAddress((void**)&q,   g_q);
    cudaGetSymbolAddress((void**)&q2,  g_q2);
    cudaGetSymbolAddress((void**)&kv,  g_kv4);
    cudaGetSymbolAddress((void**)&kv2, g_kv24);
    cudaGetSymbolAddress((void**)&wc,  g_wc);
    cudaGetSymbolAddress((void**)&bc,  g_bc);

    k_comb<<<7, 256>>>(W_proj, b_proj, W_qkv, b_qkv);
    k_linqkv<<<BB*HT*2, 352>>>(x, W_lin, b_lin, W_qkv, b_qkv);
    k_attn<0><<<128, NT>>>(q,  kv,  rpb, wc,     bc,     nullptr);
    k_attn<1><<<128, NT>>>(q2, kv2, rpb, W_proj, b_proj, out);
}

// round 15
// speedup vs baseline: 1.2737x; 1.0106x over previous
#include <cuda_runtime.h>

// 0: x [2,192,88,133] f32, 1: W_lin [133,24], 2: b_lin [24], 3: W_qkv [24,72],
// 4: b_qkv [72], 5: rpb [4,49,49], 6: W_proj [24,24], 7: b_proj [24]
// output: [2,192,88,24] f32

#define BB   2
#define HT   192
#define WD   88
#define FIN  133
#define CC   24
#define NH   4
#define DH   6
#define WIN  25
#define NPIX (BB*HT*WD)   // 33792
#define NBI  (BB*HT)      // 384
#define RPBW 49
#define TR   3            // query rows per attn block
#define NT   352          // attn threads: 88 cols x 4 heads
#define BROWS 29
#define BH   (BROWS*RPBW) // 1421
#define LOG2E 1.4426950408889634f
#define NQ   44           // quads per (bi,ch)
#define KVTQ (CC*NQ)      // 1056 quads per row tile
#define BIAS_PAD 5696     // bias region padded to 16B multiple
#define SMEM_FLOATS (BIAS_PAD + 2*KVTQ*4)   // 5696 + 8448 = 14144
#define SMEM_BYTES  (SMEM_FLOATS*4)         // 56576

typedef unsigned long long ull;

// Scratch (device globals: allocation-free). KV in quad-interleaved float4
// layout [bi][ch][44]{k0,k1,v0,v1} -> 16B-aligned LDG/STS/LDS.128.
__device__ float  g_q  [NPIX*CC];            // [bi][ch][col]
__device__ float  g_q2 [NPIX*CC];
__device__ float4 g_kv4 [NBI*CC*NQ];
__device__ float4 g_kv24[NBI*CC*NQ];
__device__ float  g_wc[CC*72], g_bc[72];

// ---- packed f32x2 helpers --------------------------------------------------
__device__ __forceinline__ ull pk2(float lo, float hi) {
    ull r; asm("mov.b64 %0, {%1,%2};" : "=l"(r) : "f"(lo), "f"(hi)); return r;
}
__device__ __forceinline__ ull bc2(float v) { return pk2(v, v); }
__device__ __forceinline__ void upk2(float& lo, float& hi, ull v) {
    asm("mov.b64 {%0,%1}, %2;" : "=f"(lo), "=f"(hi) : "l"(v));
}
__device__ __forceinline__ ull fma2(ull a, ull b, ull c) {
    ull d; asm("fma.rn.f32x2 %0, %1, %2, %3;" : "=l"(d) : "l"(a), "l"(b), "l"(c)); return d;
}
__device__ __forceinline__ ull add2(ull a, ull b) {
    ull d; asm("add.rn.f32x2 %0, %1, %2;" : "=l"(d) : "l"(a), "l"(b)); return d;
}
__device__ __forceinline__ ull mul2(ull a, ull b) {
    ull d; asm("mul.rn.f32x2 %0, %1, %2;" : "=l"(d) : "l"(a), "l"(b)); return d;
}
__device__ __forceinline__ float ex2f(float x) {
    float y; asm("ex2.approx.f32 %0, %1;" : "=f"(y) : "f"(x)); return y;
}
__device__ __forceinline__ ull lds64(const float* p) {
    return *reinterpret_cast<const ull*>(p);   // even float offset from 16B base
}

// ---------------------------------------------------------------------------
// Setup: Wcomb = W_proj @ W_qkv, bcomb = b_proj @ W_qkv + b_qkv
// (q columns scaled by dh^-0.5 * log2(e) for raw ex2 in attention)
// ---------------------------------------------------------------------------
__global__ void k_comb(const float* __restrict__ Wp, const float* __restrict__ bp,
                       const float* __restrict__ Wq, const float* __restrict__ bq) {
    int t = blockIdx.x * blockDim.x + threadIdx.x;
    const float QS = 0.40824829046386302f * LOG2E;
    if (t < CC*72) {
        int u = t / 72, cf = t % 72;
        float a = 0.f;
        #pragma unroll
        for (int w = 0; w < CC; ++w) a = fmaf(Wp[u*CC + w], Wq[w*72 + cf], a);
        if (cf < CC) a *= QS;
        g_wc[t] = a;
    }
    if (t < 72) {
        float a = bq[t];
        #pragma unroll
        for (int w = 0; w < CC; ++w) a = fmaf(bp[w], Wq[w*72 + t], a);
        if (t < CC) a *= QS;
        g_bc[t] = a;
    }
}

// ---------------------------------------------------------------------------
// Fused linear+ReLU+qkv, f32x2-packed: block = 44-pixel half row.
// Weights staged TRANSPOSED with even strides so both operands of each
// packed FMA come from LDS.64. q -> g_q, k/v -> g_kv4 (quad-interleaved).
// ---------------------------------------------------------------------------
#define XS_STR 134            // xs row stride (even)
#define WL_STR 134            // wlT row stride (even)
#define HS_STR 26             // hs row stride (even)
#define WQ_STR 26             // wqT row stride (even)

__global__ void __launch_bounds__(352) k_linqkv(const float* __restrict__ x,
                                                const float* __restrict__ Wl,
                                                const float* __restrict__ bl,
                                                const float* __restrict__ Wq,
                                                const float* __restrict__ bq) {
    __shared__ __align__(16) float sm[12128];
    float* xs  = sm;                       // 44*134 = 5896
    float* wlT = sm + 5896;                // 24*134 = 3216 (wlT[c][f])
    float* hs  = sm + 9112;                // 44*26  = 1144
    float* wqT = sm + 10256;               // 72*26  = 1872 (wqT[cf][u])

    int blk = blockIdx.x;
    int bi = blk >> 1, jb = (blk & 1) * 44;
    int tid = threadIdx.x;

    const float* xb = x + ((size_t)bi * WD + jb) * FIN;
    for (int idx = tid; idx < 44*FIN; idx += 352)
        xs[(idx / FIN) * XS_STR + (idx % FIN)] = xb[idx];
    for (int idx = tid; idx < FIN*CC; idx += 352)      // transpose W_lin
        wlT[(idx % CC) * WL_STR + (idx / CC)] = Wl[idx];
    for (int idx = tid; idx < CC*72; idx += 352)       // transpose W_qkv
        wqT[(idx % 72) * WQ_STR + (idx / 72)] = Wq[idx];
    __syncthreads();

    // Phase A: h = relu(x @ W_lin + b_lin), packed over f-pairs
    int jl = tid % 44, cg = tid / 44;      // cg in [0,8): 3 channels each
    int c0 = cg * 3;
    ull acc2[3];
    float accs[3];
    #pragma unroll
    for (int i = 0; i < 3; ++i) { acc2[i] = 0ULL; accs[i] = bl[c0 + i]; }

    const float* xrow = xs + jl * XS_STR;
    #pragma unroll 6
    for (int fp = 0; fp < 66; ++fp) {
        ull xp = lds64(xrow + 2*fp);
        #pragma unroll
        for (int i = 0; i < 3; ++i)
            acc2[i] = fma2(xp, lds64(wlT + (c0 + i)*WL_STR + 2*fp), acc2[i]);
    }
    {   // tail f = 132
        float xf = xrow[132];
        #pragma unroll
        for (int i = 0; i < 3; ++i)
            accs[i] = fmaf(xf, wlT[(c0 + i)*WL_STR + 132], accs[i]);
    }
    #pragma unroll
    for (int i = 0; i < 3; ++i) {
        float lo, hi; upk2(lo, hi, acc2[i]);
        hs[jl*HS_STR + c0 + i] = fmaxf(lo + hi + accs[i], 0.f);
    }
    __syncthreads();

    // Phase B: qkv = h @ W_qkv + b_qkv, packed over u-pairs (12 exact)
    const float QS = 0.40824829046386302f * LOG2E;
    float* kvf = reinterpret_cast<float*>(g_kv4);
    for (int o = tid; o < 44*72; o += 352) {
        int cf = o / 44, j2 = o - cf*44;
        ull a2 = 0ULL;
        const float* hrow = hs + j2 * HS_STR;
        const float* wrow = wqT + cf * WQ_STR;
        #pragma unroll
        for (int up = 0; up < 12; ++up)
            a2 = fma2(lds64(hrow + 2*up), lds64(wrow + 2*up), a2);
        float lo, hi; upk2(lo, hi, a2);
        float a = lo + hi + bq[cf];
        int which = cf / CC, ch = cf % CC;
        int j = jb + j2;
        if (which == 0) {
            g_q[((size_t)bi * CC + ch) * WD + j] = a * QS;
        } else {
            kvf[(((size_t)bi * CC + ch) * NQ + (j >> 1)) * 4 + (j & 1)
                + (which == 2 ? 2 : 0)] = a;
        }
    }
}

// ---------------------------------------------------------------------------
// Attention (TR=3, 352 thr, grid 128): K+V staged as 16B quads into a
// DOUBLE-BUFFERED dynamic-smem tile -> ONE __syncthreads per key row.
// LDS.128 -> ulonglong2 halves ARE the f32x2 operands. Split-dot chains,
// log2-domain scores, raw ex2. f32x2-packed epilogue GEMMs.
// MODE 0: epilogue -> layer-2 q/kv via Wcomb. MODE 1: final projection.
// ---------------------------------------------------------------------------
template<int MODE>
__global__ void __launch_bounds__(NT, 1) k_attn(
    const float* __restrict__ Q, const float4* __restrict__ KV,
    const float* __restrict__ rpb,
    const float* __restrict__ W, const float* __restrict__ bvec,
    float* __restrict__ outp)
{
    extern __shared__ float smem[];          // SMEM_FLOATS, 16B aligned
    float* bias_s = smem;                    // 5684 used (scaled by log2e)

    int blk = blockIdx.x;           // 128 blocks
    int b = blk >> 6, it = blk & 63;
    int i0 = it * TR;
    int tid = threadIdx.x;
    int j = tid % WD, h = tid / WD, h6 = h * DH;

    int sii[TR];
    #pragma unroll
    for (int t = 0; t < TR; ++t) sii[t] = min(max(i0 + t - 12, 0), HT - WIN);
    int r_lo = sii[0];
    int nrows = sii[2] + WIN - r_lo;           // 25..27
    int row_base = r_lo - i0 + 22;

    int sjj = min(max(j - 12, 0), WD - WIN);
    int e0 = sjj & 1;
    int c0 = sjj - e0;                          // even-aligned window start
    int qb0 = c0 >> 1;                          // quad base [0,31]
    int cb = c0 + 24 - j;                       // bias column base

    for (int idx = tid; idx < NH*BH; idx += NT) {
        int hh = idx / BH, rem = idx - hh*BH;
        int rr = rem / RPBW, c = rem - rr*RPBW;
        int src = min(max(row_base + rr, 0), RPBW - 1);
        bias_s[idx] = rpb[hh*RPBW*RPBW + src*RPBW + c] * LOG2E;
    }

    // q vectors (broadcast-packed) + negated center scores (log2 units)
    float nsc[TR];
    ull qv2[TR][DH];
    const float* KVf = reinterpret_cast<const float*>(KV);
    #pragma unroll
    for (int t = 0; t < TR; ++t) {
        const float* qp = Q + ((size_t)(b*HT + i0 + t) * CC + h6) * WD + j;
        size_t kcq = (((size_t)(b*HT + i0 + t) * CC + h6) * NQ + (j >> 1)) * 4 + (j & 1);
        float s = 0.f;
        #pragma unroll
        for (int d = 0; d < DH; ++d) {
            float qd = qp[d*WD];
            s = fmaf(qd, KVf[kcq + (size_t)d*NQ*4], s);
            qv2[t][d] = bc2(qd);
        }
        nsc[t] = -s;
    }

    // edge masks (thread-constant)
    ull mfirst = pk2(e0 ? 0.f : 1.f, 1.f);
    ull mlast  = pk2(1.f, e0 ? 1.f : 0.f);

    ull accp[TR][DH], lp[TR];
    #pragma unroll
    for (int t = 0; t < TR; ++t) {
        lp[t] = 0ULL;
        #pragma unroll
        for (int d = 0; d < DH; ++d) accp[t][d] = 0ULL;
    }

    float4* sbuf = reinterpret_cast<float4*>(smem + BIAS_PAD);

    // prefetch first row's quads (3 per thread)
    float4 kvr[3];
    {
        const float4* src = KV + (size_t)(b*HT + r_lo) * CC * NQ;
        #pragma unroll
        for (int u = 0; u < 3; ++u) kvr[u] = src[tid + u*NT];
    }

    for (int rr = 0; rr < nrows; ++rr) {
        int r = r_lo + rr;
        float4* buf = sbuf + (rr & 1) * KVTQ;
        #pragma unroll
        for (int u = 0; u < 3; ++u) buf[tid + u*NT] = kvr[u];
        __syncthreads();                      // single barrier per row
        if (rr + 1 < nrows) {
            const float4* src = KV + (size_t)(b*HT + r + 1) * CC * NQ;
            #pragma unroll
            for (int u = 0; u < 3; ++u) kvr[u] = src[tid + u*NT];
        }

        // per-row shifts (row-validity kill, log2 units)
        ull shp[TR];
        shp[0] = bc2(nsc[0] + ((r <= sii[0] + 24) ? 0.f : -87.f));
        shp[1] = bc2(nsc[1] + ((r >= sii[1] && r <= sii[1] + 24) ? 0.f : -87.f));
        shp[2] = bc2(nsc[2] + ((r >= sii[2]) ? 0.f : -87.f));

        const ulonglong2* kvp = reinterpret_cast<const ulonglong2*>(buf)
                                + h6*NQ + qb0;
        const float* br0 = bias_s + h*BH + (rr + 2)*RPBW + cb;  // query 0
        const float* br1 = br0 - RPBW;
        const float* br2 = br1 - RPBW;

        #pragma unroll
        for (int p = 0; p < 13; ++p) {
            ull kpair[DH], vpair[DH];
            #pragma unroll
            for (int d = 0; d < DH; ++d) {
                ulonglong2 u2 = kvp[d*NQ + p];   // LDS.128: {k0,k1},{v0,v1}
                kpair[d] = u2.x;
                vpair[d] = u2.y;
            }
            #pragma unroll
            for (int t = 0; t < TR; ++t) {
                const float* br = (t == 0) ? br0 : (t == 1) ? br1 : br2;
                // split-dot: two 3-chains
                ull sA = add2(pk2(br[2*p], br[2*p + 1]), shp[t]);
                #pragma unroll
                for (int d = 0; d < 3; ++d) sA = fma2(qv2[t][d], kpair[d], sA);
                ull sB = mul2(qv2[t][3], kpair[3]);
                sB = fma2(qv2[t][4], kpair[4], sB);
                sB = fma2(qv2[t][5], kpair[5], sB);
                float s0, s1; upk2(s0, s1, add2(sA, sB));
                ull pp = pk2(ex2f(s0), ex2f(s1));
                if (p == 0)  pp = mul2(pp, mfirst);
                if (p == 12) pp = mul2(pp, mlast);
                lp[t] = add2(lp[t], pp);
                #pragma unroll
                for (int d = 0; d < DH; ++d) accp[t][d] = fma2(pp, vpair[d], accp[t][d]);
            }
        }
    }

    // ---- epilogue (f32x2-packed GEMMs) -------------------------------------
    __syncthreads();
    float* attn_s = smem;                    // [3][88][25] = 6600
    const int NOUT = (MODE == 0) ? 72 : 24;
    float* ws = smem + 6600;                 // <=1728 (even offset)
    float* bs = smem + 8328;                 // <=72   (even offset)
    #pragma unroll
    for (int t = 0; t < TR; ++t) {
        float l0, l1; upk2(l0, l1, lp[t]);
        float inv = __fdividef(1.f, l0 + l1);
        #pragma unroll
        for (int d = 0; d < DH; ++d) {
            float a0, a1; upk2(a0, a1, accp[t][d]);
            attn_s[(t*WD + j)*25 + h6 + d] = (a0 + a1) * inv;
        }
    }
    for (int idx = tid; idx < CC*NOUT; idx += NT) ws[idx] = W[idx];
    for (int idx = tid; idx < NOUT; idx += NT) bs[idx] = bvec[idx];
    __syncthreads();

    if (MODE == 0) {
        float* kvo = reinterpret_cast<float*>(g_kv24);
        #pragma unroll
        for (int pass = 0; pass < 3; ++pass) {
            int cf0 = h * 18 + pass * 6;      // even; never straddles q/k/v
            ull a2[TR][3];
            #pragma unroll
            for (int t = 0; t < TR; ++t)
                #pragma unroll
                for (int cp = 0; cp < 3; ++cp) a2[t][cp] = lds64(bs + cf0 + 2*cp);
            #pragma unroll
            for (int u = 0; u < CC; ++u) {
                ull wvp[3];
                #pragma unroll
                for (int cp = 0; cp < 3; ++cp) wvp[cp] = lds64(ws + u*72 + cf0 + 2*cp);
                #pragma unroll
                for (int t = 0; t < TR; ++t) {
                    ull avb = bc2(attn_s[(t*WD + j)*25 + u]);
                    #pragma unroll
                    for (int cp = 0; cp < 3; ++cp) a2[t][cp] = fma2(avb, wvp[cp], a2[t][cp]);
                }
            }
            int which = (cf0 >= 48) ? 2 : (cf0 >= 24 ? 1 : 0);
            int chb = cf0 - which * CC;
            int voff = (which == 2) ? 2 : 0;
            #pragma unroll
            for (int t = 0; t < TR; ++t) {
                size_t bi_t = (size_t)(b*HT + i0 + t);
                #pragma unroll
                for (int cp = 0; cp < 3; ++cp) {
                    float lo, hi; upk2(lo, hi, a2[t][cp]);
                    int ci = chb + 2*cp;
                    if (which == 0) {
                        g_q2[(bi_t * CC + ci) * WD + j]     = lo;
                        g_q2[(bi_t * CC + ci + 1) * WD + j] = hi;
                    } else {
                        kvo[((bi_t * CC + ci) * NQ + (j >> 1)) * 4 + (j & 1) + voff]     = lo;
                        kvo[((bi_t * CC + ci + 1) * NQ + (j >> 1)) * 4 + (j & 1) + voff] = hi;
                    }
                }
            }
        }
    } else {
        int cf0 = h * 6;                     // even
        ull a2[TR][3];
        #pragma unroll
        for (int t = 0; t < TR; ++t)
            #pragma unroll
            for (int cp = 0; cp < 3; ++cp) a2[t][cp] = lds64(bs + cf0 + 2*cp);
        #pragma unroll
        for (int u = 0; u < CC; ++u) {
            ull wvp[3];
            #pragma unroll
            for (int cp = 0; cp < 3; ++cp) wvp[cp] = lds64(ws + u*24 + cf0 + 2*cp);
            #pragma unroll
            for (int t = 0; t < TR; ++t) {
                ull avb = bc2(attn_s[(t*WD + j)*25 + u]);
                #pragma unroll
                for (int cp = 0; cp < 3; ++cp) a2[t][cp] = fma2(avb, wvp[cp], a2[t][cp]);
            }
        }
        __syncthreads();
        float* res_s = smem;                 // [3][88][24] = 6336
        #pragma unroll
        for (int t = 0; t < TR; ++t)
            #pragma unroll
            for (int cp = 0; cp < 3; ++cp) {
                float lo, hi; upk2(lo, hi, a2[t][cp]);
                res_s[(t*WD + j)*CC + cf0 + 2*cp]     = lo;
                res_s[(t*WD + j)*CC + cf0 + 2*cp + 1] = hi;
            }
        __syncthreads();
        float* ob = outp + (size_t)(b*HT + i0) * WD * CC;
        for (int o = tid; o < TR*WD*CC; o += NT) ob[o] = res_s[o];
    }
}

// ---------------------------------------------------------------------------
extern "C" void kernel_launch(void* const* d_in, const int* in_sizes, int n_in,
                              void* d_out, int out_size) {
    (void)in_sizes; (void)n_in; (void)out_size;
    const float* x      = (const float*)d_in[0];
    const float* W_lin  = (const float*)d_in[1];
    const float* b_lin  = (const float*)d_in[2];
    const float* W_qkv  = (const float*)d_in[3];
    const float* b_qkv  = (const float*)d_in[4];
    const float* rpb    = (const float*)d_in[5];
    const float* W_proj = (const float*)d_in[6];
    const float* b_proj = (const float*)d_in[7];
    float* out = (float*)d_out;

    float *q, *q2, *wc, *bc;
    float4 *kv, *kv2;
    cudaGetSymbolAddress((void**)&q,   g_q);
    cudaGetSymbolAddress((void**)&q2,  g_q2);
    cudaGetSymbolAddress((void**)&kv,  g_kv4);
    cudaGetSymbolAddress((void**)&kv2, g_kv24);
    cudaGetSymbolAddress((void**)&wc,  g_wc);
    cudaGetSymbolAddress((void**)&bc,  g_bc);

    cudaFuncSetAttribute(k_attn<0>, cudaFuncAttributeMaxDynamicSharedMemorySize, SMEM_BYTES);
    cudaFuncSetAttribute(k_attn<1>, cudaFuncAttributeMaxDynamicSharedMemorySize, SMEM_BYTES);

    k_comb<<<7, 256>>>(W_proj, b_proj, W_qkv, b_qkv);
    k_linqkv<<<BB*HT*2, 352>>>(x, W_lin, b_lin, W_qkv, b_qkv);
    k_attn<0><<<128, NT, SMEM_BYTES>>>(q,  kv,  rpb, wc,     bc,     nullptr);
    k_attn<1><<<128, NT, SMEM_BYTES>>>(q2, kv2, rpb, W_proj, b_proj, out);
}

// round 16
// speedup vs baseline: 1.2867x; 1.0101x over previous
#include <cuda_runtime.h>

// 0: x [2,192,88,133] f32, 1: W_lin [133,24], 2: b_lin [24], 3: W_qkv [24,72],
// 4: b_qkv [72], 5: rpb [4,49,49], 6: W_proj [24,24], 7: b_proj [24]
// output: [2,192,88,24] f32

#define BB   2
#define HT   192
#define WD   88
#define FIN  133
#define CC   24
#define NH   4
#define DH   6
#define WIN  25
#define NPIX (BB*HT*WD)   // 33792
#define NBI  (BB*HT)      // 384
#define RPBW 49
#define TR   3            // query rows per attn block
#define NT   352          // attn threads: 88 cols x 4 heads
#define BROWS 29
#define BH   (BROWS*RPBW) // 1421
#define LOG2E 1.4426950408889634f
#define NQ   44           // quads per (bi,ch)
#define KVTQ (CC*NQ)      // 1056 quads per row tile
#define BIAS2_ULL (NH*BH + 2)               // 5686 packed pairs (+2 pad)
#define SMEM_BYTES (BIAS2_ULL*8 + 2*KVTQ*16) // 45488 + 33792 = 79280

typedef unsigned long long ull;

// Scratch (device globals: allocation-free). KV in quad-interleaved float4
// layout [bi][ch][44]{k0,k1,v0,v1} -> 16B-aligned LDG/STS/LDS.128.
__device__ float  g_q  [NPIX*CC];            // [bi][ch][col]
__device__ float  g_q2 [NPIX*CC];
__device__ float4 g_kv4 [NBI*CC*NQ];
__device__ float4 g_kv24[NBI*CC*NQ];
__device__ float  g_wc[CC*72], g_bc[72];

// ---- packed f32x2 helpers --------------------------------------------------
__device__ __forceinline__ ull pk2(float lo, float hi) {
    ull r; asm("mov.b64 %0, {%1,%2};" : "=l"(r) : "f"(lo), "f"(hi)); return r;
}
__device__ __forceinline__ ull bc2(float v) { return pk2(v, v); }
__device__ __forceinline__ void upk2(float& lo, float& hi, ull v) {
    asm("mov.b64 {%0,%1}, %2;" : "=f"(lo), "=f"(hi) : "l"(v));
}
__device__ __forceinline__ ull fma2(ull a, ull b, ull c) {
    ull d; asm("fma.rn.f32x2 %0, %1, %2, %3;" : "=l"(d) : "l"(a), "l"(b), "l"(c)); return d;
}
__device__ __forceinline__ ull add2(ull a, ull b) {
    ull d; asm("add.rn.f32x2 %0, %1, %2;" : "=l"(d) : "l"(a), "l"(b)); return d;
}
__device__ __forceinline__ ull mul2(ull a, ull b) {
    ull d; asm("mul.rn.f32x2 %0, %1, %2;" : "=l"(d) : "l"(a), "l"(b)); return d;
}
__device__ __forceinline__ float ex2f(float x) {
    float y; asm("ex2.approx.f32 %0, %1;" : "=f"(y) : "f"(x)); return y;
}
__device__ __forceinline__ ull lds64(const float* p) {
    return *reinterpret_cast<const ull*>(p);   // even float offset from 16B base
}

// ---------------------------------------------------------------------------
// Setup: Wcomb = W_proj @ W_qkv, bcomb = b_proj @ W_qkv + b_qkv
// (q columns scaled by dh^-0.5 * log2(e) for raw ex2 in attention)
// ---------------------------------------------------------------------------
__global__ void k_comb(const float* __restrict__ Wp, const float* __restrict__ bp,
                       const float* __restrict__ Wq, const float* __restrict__ bq) {
    int t = blockIdx.x * blockDim.x + threadIdx.x;
    const float QS = 0.40824829046386302f * LOG2E;
    if (t < CC*72) {
        int u = t / 72, cf = t % 72;
        float a = 0.f;
        #pragma unroll
        for (int w = 0; w < CC; ++w) a = fmaf(Wp[u*CC + w], Wq[w*72 + cf], a);
        if (cf < CC) a *= QS;
        g_wc[t] = a;
    }
    if (t < 72) {
        float a = bq[t];
        #pragma unroll
        for (int w = 0; w < CC; ++w) a = fmaf(bp[w], Wq[w*72 + t], a);
        if (t < CC) a *= QS;
        g_bc[t] = a;
    }
}

// ---------------------------------------------------------------------------
// Fused linear+ReLU+qkv, f32x2-packed: block = 44-pixel half row.
// Weights staged TRANSPOSED with even strides so both operands of each
// packed FMA come from LDS.64. q -> g_q, k/v -> g_kv4 (quad-interleaved).
// ---------------------------------------------------------------------------
#define XS_STR 134            // xs row stride (even)
#define WL_STR 134            // wlT row stride (even)
#define HS_STR 26             // hs row stride (even)
#define WQ_STR 26             // wqT row stride (even)

__global__ void __launch_bounds__(352) k_linqkv(const float* __restrict__ x,
                                                const float* __restrict__ Wl,
                                                const float* __restrict__ bl,
                                                const float* __restrict__ Wq,
                                                const float* __restrict__ bq) {
    __shared__ __align__(16) float sm[12128];
    float* xs  = sm;                       // 44*134 = 5896
    float* wlT = sm + 5896;                // 24*134 = 3216 (wlT[c][f])
    float* hs  = sm + 9112;                // 44*26  = 1144
    float* wqT = sm + 10256;               // 72*26  = 1872 (wqT[cf][u])

    int blk = blockIdx.x;
    int bi = blk >> 1, jb = (blk & 1) * 44;
    int tid = threadIdx.x;

    const float* xb = x + ((size_t)bi * WD + jb) * FIN;
    for (int idx = tid; idx < 44*FIN; idx += 352)
        xs[(idx / FIN) * XS_STR + (idx % FIN)] = xb[idx];
    for (int idx = tid; idx < FIN*CC; idx += 352)      // transpose W_lin
        wlT[(idx % CC) * WL_STR + (idx / CC)] = Wl[idx];
    for (int idx = tid; idx < CC*72; idx += 352)       // transpose W_qkv
        wqT[(idx % 72) * WQ_STR + (idx / 72)] = Wq[idx];
    __syncthreads();

    // Phase A: h = relu(x @ W_lin + b_lin), packed over f-pairs
    int jl = tid % 44, cg = tid / 44;      // cg in [0,8): 3 channels each
    int c0 = cg * 3;
    ull acc2[3];
    float accs[3];
    #pragma unroll
    for (int i = 0; i < 3; ++i) { acc2[i] = 0ULL; accs[i] = bl[c0 + i]; }

    const float* xrow = xs + jl * XS_STR;
    #pragma unroll 6
    for (int fp = 0; fp < 66; ++fp) {
        ull xp = lds64(xrow + 2*fp);
        #pragma unroll
        for (int i = 0; i < 3; ++i)
            acc2[i] = fma2(xp, lds64(wlT + (c0 + i)*WL_STR + 2*fp), acc2[i]);
    }
    {   // tail f = 132
        float xf = xrow[132];
        #pragma unroll
        for (int i = 0; i < 3; ++i)
            accs[i] = fmaf(xf, wlT[(c0 + i)*WL_STR + 132], accs[i]);
    }
    #pragma unroll
    for (int i = 0; i < 3; ++i) {
        float lo, hi; upk2(lo, hi, acc2[i]);
        hs[jl*HS_STR + c0 + i] = fmaxf(lo + hi + accs[i], 0.f);
    }
    __syncthreads();

    // Phase B: qkv = h @ W_qkv + b_qkv, packed over u-pairs (12 exact)
    const float QS = 0.40824829046386302f * LOG2E;
    float* kvf = reinterpret_cast<float*>(g_kv4);
    for (int o = tid; o < 44*72; o += 352) {
        int cf = o / 44, j2 = o - cf*44;
        ull a2 = 0ULL;
        const float* hrow = hs + j2 * HS_STR;
        const float* wrow = wqT + cf * WQ_STR;
        #pragma unroll
        for (int up = 0; up < 12; ++up)
            a2 = fma2(lds64(hrow + 2*up), lds64(wrow + 2*up), a2);
        float lo, hi; upk2(lo, hi, a2);
        float a = lo + hi + bq[cf];
        int which = cf / CC, ch = cf % CC;
        int j = jb + j2;
        if (which == 0) {
            g_q[((size_t)bi * CC + ch) * WD + j] = a * QS;
        } else {
            kvf[(((size_t)bi * CC + ch) * NQ + (j >> 1)) * 4 + (j & 1)
                + (which == 2 ? 2 : 0)] = a;
        }
    }
}

// ---------------------------------------------------------------------------
// Attention (TR=3, 352 thr, grid 128): K+V staged as 16B quads into a
// DOUBLE-BUFFERED dynamic-smem tile -> ONE __syncthreads per key row.
// Bias pre-packed as OVERLAPPING f32x2 pairs (one LDS.64 per score pair,
// any window parity). LDS.128 -> ulonglong2 halves ARE the f32x2 operands.
// Split-dot chains, log2-domain scores, raw ex2. Packed epilogue GEMMs.
// MODE 0: epilogue -> layer-2 q/kv via Wcomb. MODE 1: final projection.
// ---------------------------------------------------------------------------
template<int MODE>
__global__ void __launch_bounds__(NT, 1) k_attn(
    const float* __restrict__ Q, const float4* __restrict__ KV,
    const float* __restrict__ rpb,
    const float* __restrict__ W, const float* __restrict__ bvec,
    float* __restrict__ outp)
{
    extern __shared__ float smem[];          // dynamic, 16B aligned
    ull* bias2 = reinterpret_cast<ull*>(smem);           // BIAS2_ULL pairs

    int blk = blockIdx.x;           // 128 blocks
    int b = blk >> 6, it = blk & 63;
    int i0 = it * TR;
    int tid = threadIdx.x;
    int j = tid % WD, h = tid / WD, h6 = h * DH;

    int sii[TR];
    #pragma unroll
    for (int t = 0; t < TR; ++t) sii[t] = min(max(i0 + t - 12, 0), HT - WIN);
    int r_lo = sii[0];
    int nrows = sii[2] + WIN - r_lo;           // 25..27
    int row_base = r_lo - i0 + 22;

    int sjj = min(max(j - 12, 0), WD - WIN);
    int e0 = sjj & 1;
    int c0 = sjj - e0;                          // even-aligned window start
    int qb0 = c0 >> 1;                          // quad base [0,31]
    int cb = c0 + 24 - j;                       // bias column base (>= -1)

    // Stage overlapping packed bias pairs: bias2[hh][rr][c] = {b[c], b[c+1]}
    for (int idx = tid; idx < NH*BH; idx += NT) {
        int hh = idx / BH, rem = idx - hh*BH;
        int rr = rem / RPBW, c = rem - rr*RPBW;
        int src = min(max(row_base + rr, 0), RPBW - 1);
        const float* rp = rpb + hh*RPBW*RPBW + src*RPBW;
        float lo = rp[c] * LOG2E;
        float hi = (c < RPBW - 1) ? rp[c + 1] * LOG2E : 0.f;
        bias2[idx] = pk2(lo, hi);
    }
    if (tid < 2) bias2[NH*BH + tid] = 0ULL;    // pad (masked edge reads)

    // q vectors (broadcast-packed) + negated center scores (log2 units)
    float nsc[TR];
    ull qv2[TR][DH];
    const float* KVf = reinterpret_cast<const float*>(KV);
    #pragma unroll
    for (int t = 0; t < TR; ++t) {
        const float* qp = Q + ((size_t)(b*HT + i0 + t) * CC + h6) * WD + j;
        size_t kcq = (((size_t)(b*HT + i0 + t) * CC + h6) * NQ + (j >> 1)) * 4 + (j & 1);
        float s = 0.f;
        #pragma unroll
        for (int d = 0; d < DH; ++d) {
            float qd = qp[d*WD];
            s = fmaf(qd, KVf[kcq + (size_t)d*NQ*4], s);
            qv2[t][d] = bc2(qd);
        }
        nsc[t] = -s;
    }

    // edge masks (thread-constant)
    ull mfirst = pk2(e0 ? 0.f : 1.f, 1.f);
    ull mlast  = pk2(1.f, e0 ? 1.f : 0.f);

    ull accp[TR][DH], lp[TR];
    #pragma unroll
    for (int t = 0; t < TR; ++t) {
        lp[t] = 0ULL;
        #pragma unroll
        for (int d = 0; d < DH; ++d) accp[t][d] = 0ULL;
    }

    float4* sbuf = reinterpret_cast<float4*>(smem + BIAS2_ULL*2);

    // prefetch first row's quads (3 per thread)
    float4 kvr[3];
    {
        const float4* src = KV + (size_t)(b*HT + r_lo) * CC * NQ;
        #pragma unroll
        for (int u = 0; u < 3; ++u) kvr[u] = src[tid + u*NT];
    }

    for (int rr = 0; rr < nrows; ++rr) {
        int r = r_lo + rr;
        float4* buf = sbuf + (rr & 1) * KVTQ;
        #pragma unroll
        for (int u = 0; u < 3; ++u) buf[tid + u*NT] = kvr[u];
        __syncthreads();                      // single barrier per row
        if (rr + 1 < nrows) {
            const float4* src = KV + (size_t)(b*HT + r + 1) * CC * NQ;
            #pragma unroll
            for (int u = 0; u < 3; ++u) kvr[u] = src[tid + u*NT];
        }

        // per-row shifts (row-validity kill, log2 units)
        ull shp[TR];
        shp[0] = bc2(nsc[0] + ((r <= sii[0] + 24) ? 0.f : -87.f));
        shp[1] = bc2(nsc[1] + ((r >= sii[1] && r <= sii[1] + 24) ? 0.f : -87.f));
        shp[2] = bc2(nsc[2] + ((r >= sii[2]) ? 0.f : -87.f));

        const ulonglong2* kvp = reinterpret_cast<const ulonglong2*>(buf)
                                + h6*NQ + qb0;
        const ull* bb0 = bias2 + h*BH + (rr + 2)*RPBW + cb;  // query 0
        const ull* bb1 = bb0 - RPBW;
        const ull* bb2 = bb1 - RPBW;

        #pragma unroll
        for (int p = 0; p < 13; ++p) {
            ull kpair[DH], vpair[DH];
            #pragma unroll
            for (int d = 0; d < DH; ++d) {
                ulonglong2 u2 = kvp[d*NQ + p];   // LDS.128: {k0,k1},{v0,v1}
                kpair[d] = u2.x;
                vpair[d] = u2.y;
            }
            #pragma unroll
            for (int t = 0; t < TR; ++t) {
                const ull* bb = (t == 0) ? bb0 : (t == 1) ? bb1 : bb2;
                // split-dot: two 3-chains; bias pair via single LDS.64
                ull sA = add2(bb[2*p], shp[t]);
                #pragma unroll
                for (int d = 0; d < 3; ++d) sA = fma2(qv2[t][d], kpair[d], sA);
                ull sB = mul2(qv2[t][3], kpair[3]);
                sB = fma2(qv2[t][4], kpair[4], sB);
                sB = fma2(qv2[t][5], kpair[5], sB);
                float s0, s1; upk2(s0, s1, add2(sA, sB));
                ull pp = pk2(ex2f(s0), ex2f(s1));
                if (p == 0)  pp = mul2(pp, mfirst);
                if (p == 12) pp = mul2(pp, mlast);
                lp[t] = add2(lp[t], pp);
                #pragma unroll
                for (int d = 0; d < DH; ++d) accp[t][d] = fma2(pp, vpair[d], accp[t][d]);
            }
        }
    }

    // ---- epilogue (f32x2-packed GEMMs; reuses smem as float region) --------
    __syncthreads();
    float* attn_s = smem;                    // [3][88][25] = 6600
    const int NOUT = (MODE == 0) ? 72 : 24;
    float* ws = smem + 6600;                 // <=1728 (even offset)
    float* bs = smem + 8328;                 // <=72   (even offset)
    #pragma unroll
    for (int t = 0; t < TR; ++t) {
        float l0, l1; upk2(l0, l1, lp[t]);
        float inv = __fdividef(1.f, l0 + l1);
        #pragma unroll
        for (int d = 0; d < DH; ++d) {
            float a0, a1; upk2(a0, a1, accp[t][d]);
            attn_s[(t*WD + j)*25 + h6 + d] = (a0 + a1) * inv;
        }
    }
    for (int idx = tid; idx < CC*NOUT; idx += NT) ws[idx] = W[idx];
    for (int idx = tid; idx < NOUT; idx += NT) bs[idx] = bvec[idx];
    __syncthreads();

    if (MODE == 0) {
        float* kvo = reinterpret_cast<float*>(g_kv24);
        #pragma unroll
        for (int pass = 0; pass < 3; ++pass) {
            int cf0 = h * 18 + pass * 6;      // even; never straddles q/k/v
            ull a2[TR][3];
            #pragma unroll
            for (int t = 0; t < TR; ++t)
                #pragma unroll
                for (int cp = 0; cp < 3; ++cp) a2[t][cp] = lds64(bs + cf0 + 2*cp);
            #pragma unroll
            for (int u = 0; u < CC; ++u) {
                ull wvp[3];
                #pragma unroll
                for (int cp = 0; cp < 3; ++cp) wvp[cp] = lds64(ws + u*72 + cf0 + 2*cp);
                #pragma unroll
                for (int t = 0; t < TR; ++t) {
                    ull avb = bc2(attn_s[(t*WD + j)*25 + u]);
                    #pragma unroll
                    for (int cp = 0; cp < 3; ++cp) a2[t][cp] = fma2(avb, wvp[cp], a2[t][cp]);
                }
            }
            int which = (cf0 >= 48) ? 2 : (cf0 >= 24 ? 1 : 0);
            int chb = cf0 - which * CC;
            int voff = (which == 2) ? 2 : 0;
            #pragma unroll
            for (int t = 0; t < TR; ++t) {
                size_t bi_t = (size_t)(b*HT + i0 + t);
                #pragma unroll
                for (int cp = 0; cp < 3; ++cp) {
                    float lo, hi; upk2(lo, hi, a2[t][cp]);
                    int ci = chb + 2*cp;
                    if (which == 0) {
                        g_q2[(bi_t * CC + ci) * WD + j]     = lo;
                        g_q2[(bi_t * CC + ci + 1) * WD + j] = hi;
                    } else {
                        kvo[((bi_t * CC + ci) * NQ + (j >> 1)) * 4 + (j & 1) + voff]     = lo;
                        kvo[((bi_t * CC + ci + 1) * NQ + (j >> 1)) * 4 + (j & 1) + voff] = hi;
                    }
                }
            }
        }
    } else {
        int cf0 = h * 6;                     // even
        ull a2[TR][3];
        #pragma unroll
        for (int t = 0; t < TR; ++t)
            #pragma unroll
            for (int cp = 0; cp < 3; ++cp) a2[t][cp] = lds64(bs + cf0 + 2*cp);
        #pragma unroll
        for (int u = 0; u < CC; ++u) {
            ull wvp[3];
            #pragma unroll
            for (int cp = 0; cp < 3; ++cp) wvp[cp] = lds64(ws + u*24 + cf0 + 2*cp);
            #pragma unroll
            for (int t = 0; t < TR; ++t) {
                ull avb = bc2(attn_s[(t*WD + j)*25 + u]);
                #pragma unroll
                for (int cp = 0; cp < 3; ++cp) a2[t][cp] = fma2(avb, wvp[cp], a2[t][cp]);
            }
        }
        __syncthreads();
        float* res_s = smem;                 // [3][88][24] = 6336
        #pragma unroll
        for (int t = 0; t < TR; ++t)
            #pragma unroll
            for (int cp = 0; cp < 3; ++cp) {
                float lo, hi; upk2(lo, hi, a2[t][cp]);
                res_s[(t*WD + j)*CC + cf0 + 2*cp]     = lo;
                res_s[(t*WD + j)*CC + cf0 + 2*cp + 1] = hi;
            }
        __syncthreads();
        float* ob = outp + (size_t)(b*HT + i0) * WD * CC;
        for (int o = tid; o < TR*WD*CC; o += NT) ob[o] = res_s[o];
    }
}

// ---------------------------------------------------------------------------
extern "C" void kernel_launch(void* const* d_in, const int* in_sizes, int n_in,
                              void* d_out, int out_size) {
    (void)in_sizes; (void)n_in; (void)out_size;
    const float* x      = (const float*)d_in[0];
    const float* W_lin  = (const float*)d_in[1];
    const float* b_lin  = (const float*)d_in[2];
    const float* W_qkv  = (const float*)d_in[3];
    const float* b_qkv  = (const float*)d_in[4];
    const float* rpb    = (const float*)d_in[5];
    const float* W_proj = (const float*)d_in[6];
    const float* b_proj = (const float*)d_in[7];
    float* out = (float*)d_out;

    float *q, *q2, *wc, *bc;
    float4 *kv, *kv2;
    cudaGetSymbolAddress((void**)&q,   g_q);
    cudaGetSymbolAddress((void**)&q2,  g_q2);
    cudaGetSymbolAddress((void**)&kv,  g_kv4);
    cudaGetSymbolAddress((void**)&kv2, g_kv24);
    cudaGetSymbolAddress((void**)&wc,  g_wc);
    cudaGetSymbolAddress((void**)&bc,  g_bc);

    cudaFuncSetAttribute(k_attn<0>, cudaFuncAttributeMaxDynamicSharedMemorySize, SMEM_BYTES);
    cudaFuncSetAttribute(k_attn<1>, cudaFuncAttributeMaxDynamicSharedMemorySize, SMEM_BYTES);

    k_comb<<<7, 256>>>(W_proj, b_proj, W_qkv, b_qkv);
    k_linqkv<<<BB*HT*2, 352>>>(x, W_lin, b_lin, W_qkv, b_qkv);
    k_attn<0><<<128, NT, SMEM_BYTES>>>(q,  kv,  rpb, wc,     bc,     nullptr);
    k_attn<1><<<128, NT, SMEM_BYTES>>>(q2, kv2, rpb, W_proj, b_proj, out);
}